// round 6
// baseline (speedup 1.0000x reference)
#include <cuda_runtime.h>
#include <cuda_fp16.h>
#include <math.h>
#include <cstdint>

#define BATCH 2
#define SEQ   2048
#define HID   2048
#define NHEAD 16
#define HDIM  128
#define FFD   8192
#define ROWS  (BATCH*SEQ)   // 4096

// ---------------- scratch ---------------------------------------------------
__device__ float g_q [ROWS*HID];
__device__ float g_k [ROWS*HID];
__device__ float g_v [ROWS*HID];
__device__ float g_h [ROWS*HID];
__device__ __half g_xnh[ROWS*HID];
__device__ __half g_xnl[ROWS*HID];
__device__ __half g_atth[ROWS*HID];
__device__ __half g_attl[ROWS*HID];
__device__ __half g_hnh[ROWS*HID];
__device__ __half g_hnl[ROWS*HID];
__device__ __half g_ffh[(size_t)ROWS*FFD];
__device__ __half g_ffl[(size_t)ROWS*FFD];
__device__ __half g_wqh[HID*HID];   __device__ __half g_wql[HID*HID];
__device__ __half g_wkh[HID*HID];   __device__ __half g_wkl[HID*HID];
__device__ __half g_wvh[HID*HID];   __device__ __half g_wvl[HID*HID];
__device__ __half g_woh[HID*HID];   __device__ __half g_wol[HID*HID];
__device__ __half g_winh[(size_t)HID*FFD];  __device__ __half g_winl[(size_t)HID*FFD];
__device__ __half g_wouth[(size_t)HID*FFD]; __device__ __half g_woutl[(size_t)HID*FFD];

// ============================ helpers ========================================
__device__ __forceinline__ uint32_t smem_u32(const void* p) {
    uint32_t a;
    asm("{ .reg .u64 t; cvta.to.shared.u64 t, %1; cvt.u32.u64 %0, t; }"
        : "=r"(a) : "l"(p));
    return a;
}
__device__ __forceinline__ void cp16(uint32_t dst, const void* src) {
    asm volatile("cp.async.cg.shared.global [%0], [%1], 16;" :: "r"(dst), "l"(src));
}
__device__ __forceinline__ void cp_commit() { asm volatile("cp.async.commit_group;"); }
template<int N> __device__ __forceinline__ void cp_wait() {
    asm volatile("cp.async.wait_group %0;" :: "n"(N));
}
__device__ __forceinline__ void ldsm_x4(uint32_t* r, uint32_t addr) {
    asm volatile("ldmatrix.sync.aligned.m8n8.x4.shared.b16 {%0,%1,%2,%3}, [%4];"
        : "=r"(r[0]), "=r"(r[1]), "=r"(r[2]), "=r"(r[3]) : "r"(addr));
}
__device__ __forceinline__ void ldsm_x4_t(uint32_t* r, uint32_t addr) {
    asm volatile("ldmatrix.sync.aligned.m8n8.x4.trans.shared.b16 {%0,%1,%2,%3}, [%4];"
        : "=r"(r[0]), "=r"(r[1]), "=r"(r[2]), "=r"(r[3]) : "r"(addr));
}
__device__ __forceinline__ void mma_f16(float* c, const uint32_t* a, const uint32_t* b) {
    asm volatile("mma.sync.aligned.m16n8k16.row.col.f32.f16.f16.f32 "
        "{%0,%1,%2,%3}, {%4,%5,%6,%7}, {%8,%9}, {%0,%1,%2,%3};"
        : "+f"(c[0]), "+f"(c[1]), "+f"(c[2]), "+f"(c[3])
        : "r"(a[0]), "r"(a[1]), "r"(a[2]), "r"(a[3]), "r"(b[0]), "r"(b[1]));
}
__device__ __forceinline__ float gelu_tanh(float x) {
    float x3 = x * x * x;
    float t  = tanhf(0.7978845608028654f * (x + 0.044715f * x3));
    return 0.5f * x * (1.0f + t);
}
__device__ __forceinline__ void split_val(float v, __half& hi, __half& lo) {
    hi = __float2half_rn(v);
    lo = __float2half_rn(v - __half2float(hi));
}

// ============================================================================
// split-fp16 tensor-core GEMM (3-term): C = Ahi*Bhi + Ahi*Blo + Alo*Bhi
// Term-major MMA issue order -> no dependent back-to-back HMMA on same acc.
// ============================================================================
#define BM 128
#define BN 128
#define BKH 32
#define LDAH 40
#define LDBH 136
#define ASZH (BM*LDAH)
#define BSZH (BKH*LDBH)
#define STG 5
#define STAGEH (2*ASZH + 2*BSZH)
#define GEMM_SMEM (STG*STAGEH*2)

template<int ACT>
__global__ __launch_bounds__(256) void tc_gemm(
    const __half* __restrict__ Ahi, const __half* __restrict__ Alo,
    const __half* __restrict__ Bhi, const __half* __restrict__ Blo,
    const float* __restrict__ Res, float* __restrict__ Cf,
    __half* __restrict__ Chi, __half* __restrict__ Clo,
    int N_, int K)
{
    extern __shared__ __align__(16) __half smem[];

    const int tid  = threadIdx.x;
    const int wid  = tid >> 5;
    const int lane = tid & 31;
    const int gid  = lane >> 2;
    const int tg   = lane & 3;
    const int wm   = wid & 3;
    const int wn   = wid >> 2;
    const int bm = blockIdx.y * BM;
    const int bn = blockIdx.x * BN;
    const int nK = K / BKH;

    const int a_m = lane & 15;
    const int a_k = (lane >> 4) * 8;
    const int b_k = ((lane >> 3) & 1) * 8 + (lane & 7);
    const int b_n = (lane >> 4) * 8;

    auto load_stage = [&](int s, int kt) {
        const int k0 = kt * BKH;
        __half* Ah = smem + s*STAGEH;
        __half* Al = Ah + ASZH;
        __half* Bh = Al + ASZH;
        __half* Bl = Bh + BSZH;
        #pragma unroll
        for (int i = 0; i < 2; i++) {
            const int c  = tid + 256*i;
            const int ar = c >> 2, ak = (c & 3) << 3;
            cp16(smem_u32(&Ah[ar*LDAH + ak]), &Ahi[(size_t)(bm + ar)*K + k0 + ak]);
            cp16(smem_u32(&Al[ar*LDAH + ak]), &Alo[(size_t)(bm + ar)*K + k0 + ak]);
            const int bk = c >> 4, bnn = (c & 15) << 3;
            cp16(smem_u32(&Bh[bk*LDBH + bnn]), &Bhi[(size_t)(k0 + bk)*N_ + bn + bnn]);
            cp16(smem_u32(&Bl[bk*LDBH + bnn]), &Blo[(size_t)(k0 + bk)*N_ + bn + bnn]);
        }
        cp_commit();
    };

    float acc[2][8][4];
    #pragma unroll
    for (int mt = 0; mt < 2; mt++)
        #pragma unroll
        for (int nt = 0; nt < 8; nt++)
            #pragma unroll
            for (int r = 0; r < 4; r++) acc[mt][nt][r] = 0.0f;

    #pragma unroll
    for (int s = 0; s < STG-1; s++) load_stage(s, s);

    for (int kt = 0; kt < nK; kt++) {
        cp_wait<STG-2>();
        __syncthreads();
        const int s = kt % STG;
        const __half* Ah = smem + s*STAGEH;
        const __half* Al = Ah + ASZH;
        const __half* Bh = Al + ASZH;
        const __half* Bl = Bh + BSZH;

        #pragma unroll
        for (int kk = 0; kk < 2; kk++) {
            uint32_t ah[2][4], al[2][4];
            #pragma unroll
            for (int mt = 0; mt < 2; mt++) {
                const int mrow = wm*32 + mt*16 + a_m;
                const int koff = kk*16 + a_k;
                ldsm_x4(ah[mt], smem_u32(&Ah[mrow*LDAH + koff]));
                ldsm_x4(al[mt], smem_u32(&Al[mrow*LDAH + koff]));
            }
            uint32_t bh[4][4], bl[4][4];
            #pragma unroll
            for (int ng = 0; ng < 4; ng++) {
                const int koff = kk*16 + b_k;
                const int noff = wn*64 + ng*16 + b_n;
                ldsm_x4_t(bh[ng], smem_u32(&Bh[koff*LDBH + noff]));
                ldsm_x4_t(bl[ng], smem_u32(&Bl[koff*LDBH + noff]));
            }
            if (kk == 0 && kt + STG - 1 < nK)
                load_stage((kt + STG - 1) % STG, kt + STG - 1);

            #pragma unroll
            for (int mt = 0; mt < 2; mt++)
                #pragma unroll
                for (int nt = 0; nt < 8; nt++)
                    mma_f16(acc[mt][nt], ah[mt], &bh[nt >> 1][(nt & 1) * 2]);
            #pragma unroll
            for (int mt = 0; mt < 2; mt++)
                #pragma unroll
                for (int nt = 0; nt < 8; nt++)
                    mma_f16(acc[mt][nt], ah[mt], &bl[nt >> 1][(nt & 1) * 2]);
            #pragma unroll
            for (int mt = 0; mt < 2; mt++)
                #pragma unroll
                for (int nt = 0; nt < 8; nt++)
                    mma_f16(acc[mt][nt], al[mt], &bh[nt >> 1][(nt & 1) * 2]);
        }
    }

    #pragma unroll
    for (int mt = 0; mt < 2; mt++) {
        #pragma unroll
        for (int half_ = 0; half_ < 2; half_++) {
            const int r = bm + wm*32 + mt*16 + gid + half_*8;
            #pragma unroll
            for (int nt = 0; nt < 8; nt++) {
                const int cc = bn + wn*64 + nt*8 + tg*2;
                float v0 = acc[mt][nt][half_*2 + 0];
                float v1 = acc[mt][nt][half_*2 + 1];
                if (ACT == 2) {
                    v0 = gelu_tanh(v0); v1 = gelu_tanh(v1);
                    __half h0, l0, h1, l1;
                    split_val(v0, h0, l0); split_val(v1, h1, l1);
                    *reinterpret_cast<__half2*>(&Chi[(size_t)r*N_ + cc]) = __halves2half2(h0, h1);
                    *reinterpret_cast<__half2*>(&Clo[(size_t)r*N_ + cc]) = __halves2half2(l0, l1);
                } else {
                    if (ACT == 1) {
                        const float2 rr = *reinterpret_cast<const float2*>(&Res[(size_t)r*N_ + cc]);
                        v0 += rr.x; v1 += rr.y;
                    }
                    float2 o; o.x = v0; o.y = v1;
                    *reinterpret_cast<float2*>(&Cf[(size_t)r*N_ + cc]) = o;
                }
            }
        }
    }
}

// ------------- weight split: merged launches --------------------------------
__global__ void split4_kernel(const float* __restrict__ w0, __half* h0, __half* l0,
                              const float* __restrict__ w1, __half* h1, __half* l1,
                              const float* __restrict__ w2, __half* h2, __half* l2,
                              const float* __restrict__ w3, __half* h3, __half* l3,
                              int n4)
{
    const float* in; __half* hi; __half* lo;
    switch (blockIdx.y) {
        case 0: in = w0; hi = h0; lo = l0; break;
        case 1: in = w1; hi = h1; lo = l1; break;
        case 2: in = w2; hi = h2; lo = l2; break;
        default: in = w3; hi = h3; lo = l3; break;
    }
    const int i = blockIdx.x*blockDim.x + threadIdx.x;
    if (i >= n4) return;
    float4 v = reinterpret_cast<const float4*>(in)[i];
    __half a0,b0,a1,b1,a2,b2,a3,b3;
    split_val(v.x, a0, b0); split_val(v.y, a1, b1);
    split_val(v.z, a2, b2); split_val(v.w, a3, b3);
    reinterpret_cast<__half2*>(hi)[2*i+0] = __halves2half2(a0, a1);
    reinterpret_cast<__half2*>(hi)[2*i+1] = __halves2half2(a2, a3);
    reinterpret_cast<__half2*>(lo)[2*i+0] = __halves2half2(b0, b1);
    reinterpret_cast<__half2*>(lo)[2*i+1] = __halves2half2(b2, b3);
}
__global__ void split2_kernel(const float* __restrict__ w0, __half* h0, __half* l0,
                              const float* __restrict__ w1, __half* h1, __half* l1,
                              int n4)
{
    const float* in = blockIdx.y ? w1 : w0;
    __half* hi = blockIdx.y ? h1 : h0;
    __half* lo = blockIdx.y ? l1 : l0;
    const int i = blockIdx.x*blockDim.x + threadIdx.x;
    if (i >= n4) return;
    float4 v = reinterpret_cast<const float4*>(in)[i];
    __half a0,b0,a1,b1,a2,b2,a3,b3;
    split_val(v.x, a0, b0); split_val(v.y, a1, b1);
    split_val(v.z, a2, b2); split_val(v.w, a3, b3);
    reinterpret_cast<__half2*>(hi)[2*i+0] = __halves2half2(a0, a1);
    reinterpret_cast<__half2*>(hi)[2*i+1] = __halves2half2(a2, a3);
    reinterpret_cast<__half2*>(lo)[2*i+0] = __halves2half2(b0, b1);
    reinterpret_cast<__half2*>(lo)[2*i+1] = __halves2half2(b2, b3);
}

// ---------------- LayerNorm -> split fp16 outputs ---------------------------
__global__ void ln_kernel(const float* __restrict__ x,
                          const float* __restrict__ g,
                          const float* __restrict__ b,
                          __half* __restrict__ ohi, __half* __restrict__ olo)
{
    const int row = blockIdx.x;
    const int tid = threadIdx.x;
    const float* xr = x + (size_t)row * HID;

    float4 v0 = reinterpret_cast<const float4*>(xr)[tid];
    float4 v1 = reinterpret_cast<const float4*>(xr)[tid + 256];

    __shared__ float red[8];

    float s = v0.x+v0.y+v0.z+v0.w + v1.x+v1.y+v1.z+v1.w;
    #pragma unroll
    for (int o = 16; o > 0; o >>= 1) s += __shfl_xor_sync(0xffffffffu, s, o);
    if ((tid & 31) == 0) red[tid >> 5] = s;
    __syncthreads();
    float mu = (red[0]+red[1]+red[2]+red[3]+red[4]+red[5]+red[6]+red[7]) * (1.0f/HID);
    __syncthreads();

    float d0x=v0.x-mu, d0y=v0.y-mu, d0z=v0.z-mu, d0w=v0.w-mu;
    float d1x=v1.x-mu, d1y=v1.y-mu, d1z=v1.z-mu, d1w=v1.w-mu;
    float sq = d0x*d0x+d0y*d0y+d0z*d0z+d0w*d0w + d1x*d1x+d1y*d1y+d1z*d1z+d1w*d1w;
    #pragma unroll
    for (int o = 16; o > 0; o >>= 1) sq += __shfl_xor_sync(0xffffffffu, sq, o);
    if ((tid & 31) == 0) red[tid >> 5] = sq;
    __syncthreads();
    float var = (red[0]+red[1]+red[2]+red[3]+red[4]+red[5]+red[6]+red[7]) * (1.0f/HID);
    float rstd = rsqrtf(var + 1e-5f);

    float4 g0 = reinterpret_cast<const float4*>(g)[tid];
    float4 g1 = reinterpret_cast<const float4*>(g)[tid + 256];
    float4 b0 = reinterpret_cast<const float4*>(b)[tid];
    float4 b1 = reinterpret_cast<const float4*>(b)[tid + 256];

    float o0[4] = { d0x*rstd*g0.x + b0.x, d0y*rstd*g0.y + b0.y,
                    d0z*rstd*g0.z + b0.z, d0w*rstd*g0.w + b0.w };
    float o1[4] = { d1x*rstd*g1.x + b1.x, d1y*rstd*g1.y + b1.y,
                    d1z*rstd*g1.z + b1.z, d1w*rstd*g1.w + b1.w };

    const size_t base = (size_t)row * HID;
    __half h[4], l[4];
    #pragma unroll
    for (int j = 0; j < 4; j++) split_val(o0[j], h[j], l[j]);
    reinterpret_cast<__half2*>(ohi + base)[tid*2+0] = __halves2half2(h[0], h[1]);
    reinterpret_cast<__half2*>(ohi + base)[tid*2+1] = __halves2half2(h[2], h[3]);
    reinterpret_cast<__half2*>(olo + base)[tid*2+0] = __halves2half2(l[0], l[1]);
    reinterpret_cast<__half2*>(olo + base)[tid*2+1] = __halves2half2(l[2], l[3]);
    #pragma unroll
    for (int j = 0; j < 4; j++) split_val(o1[j], h[j], l[j]);
    reinterpret_cast<__half2*>(ohi + base)[(tid+256)*2+0] = __halves2half2(h[0], h[1]);
    reinterpret_cast<__half2*>(ohi + base)[(tid+256)*2+1] = __halves2half2(h[2], h[3]);
    reinterpret_cast<__half2*>(olo + base)[(tid+256)*2+0] = __halves2half2(l[0], l[1]);
    reinterpret_cast<__half2*>(olo + base)[(tid+256)*2+1] = __halves2half2(l[2], l[3]);
}

// ---------------- Flash attention (causal, fp32) ----------------------------
#define QSTRIDE 132
#define KSTRIDE 68
#define PSTRIDE 68

__global__ __launch_bounds__(256) void flash_kernel(
    const float* __restrict__ Q, const float* __restrict__ K,
    const float* __restrict__ V,
    __half* __restrict__ Ohi, __half* __restrict__ Olo)
{
    extern __shared__ float sm[];
    float* Qs = sm;
    float* Kt = Qs + 64*QSTRIDE;
    float* Vs = Kt + 128*KSTRIDE;
    float* Ps = Vs + 64*QSTRIDE;

    const int tid = threadIdx.x;
    const int tx = tid & 15;
    const int ty = tid >> 4;
    const int bh = blockIdx.y;
    const int b  = bh >> 4;
    const int h  = bh & 15;
    const int qb = blockIdx.x;
    const size_t rowbase = (size_t)b * SEQ;
    const int colbase = h * HDIM;
    const float scale = 0.088388347648318447f;

    #pragma unroll
    for (int it = 0; it < 8; ++it) {
        int idx = it * 256 + tid;
        int r  = idx >> 5;
        int c4 = (idx & 31) << 2;
        float4 qv = *reinterpret_cast<const float4*>(
            &Q[(rowbase + qb*64 + r) * HID + colbase + c4]);
        *reinterpret_cast<float4*>(&Qs[r*QSTRIDE + c4]) = qv;
    }

    float m[4], l[4], o[4][8];
    #pragma unroll
    for (int i = 0; i < 4; i++) {
        m[i] = -1e30f; l[i] = 0.0f;
        #pragma unroll
        for (int c = 0; c < 8; c++) o[i][c] = 0.0f;
    }

    for (int kb = 0; kb <= qb; ++kb) {
        __syncthreads();
        #pragma unroll
        for (int it = 0; it < 8; ++it) {
            int idx = it * 256 + tid;
            int r  = idx >> 5;
            int c4 = (idx & 31) << 2;
            const size_t grow = (rowbase + kb*64 + r) * (size_t)HID + colbase + c4;
            float4 kv = *reinterpret_cast<const float4*>(&K[grow]);
            Kt[(c4+0)*KSTRIDE + r] = kv.x;
            Kt[(c4+1)*KSTRIDE + r] = kv.y;
            Kt[(c4+2)*KSTRIDE + r] = kv.z;
            Kt[(c4+3)*KSTRIDE + r] = kv.w;
            float4 vv = *reinterpret_cast<const float4*>(&V[grow]);
            *reinterpret_cast<float4*>(&Vs[r*QSTRIDE + c4]) = vv;
        }
        __syncthreads();

        float s[4][4];
        #pragma unroll
        for (int i = 0; i < 4; i++)
            #pragma unroll
            for (int jj = 0; jj < 4; jj++) s[i][jj] = 0.0f;

        #pragma unroll 4
        for (int d = 0; d < HDIM; ++d) {
            const float4 kr = *reinterpret_cast<const float4*>(&Kt[d*KSTRIDE + tx*4]);
            #pragma unroll
            for (int i = 0; i < 4; i++) {
                const float qv = Qs[(ty*4 + i)*QSTRIDE + d];
                s[i][0] = fmaf(qv, kr.x, s[i][0]);
                s[i][1] = fmaf(qv, kr.y, s[i][1]);
                s[i][2] = fmaf(qv, kr.z, s[i][2]);
                s[i][3] = fmaf(qv, kr.w, s[i][3]);
            }
        }

        const bool diag = (kb == qb);
        #pragma unroll
        for (int i = 0; i < 4; i++) {
            const int qg = qb*64 + ty*4 + i;
            float mx = -1e30f;
            #pragma unroll
            for (int jj = 0; jj < 4; jj++) {
                float v = s[i][jj] * scale;
                if (diag && (kb*64 + tx*4 + jj) > qg) v = -1e30f;
                s[i][jj] = v;
                mx = fmaxf(mx, v);
            }
            #pragma unroll
            for (int off = 8; off > 0; off >>= 1)
                mx = fmaxf(mx, __shfl_xor_sync(0xffffffffu, mx, off));
            float mnew = fmaxf(m[i], mx);
            float corr = __expf(m[i] - mnew);
            float rs = 0.0f;
            #pragma unroll
            for (int jj = 0; jj < 4; jj++) {
                float p = __expf(s[i][jj] - mnew);
                s[i][jj] = p;
                rs += p;
            }
            #pragma unroll
            for (int off = 8; off > 0; off >>= 1)
                rs += __shfl_xor_sync(0xffffffffu, rs, off);
            l[i] = l[i]*corr + rs;
            m[i] = mnew;
            #pragma unroll
            for (int c = 0; c < 8; c++) o[i][c] *= corr;
            float4 pv; pv.x = s[i][0]; pv.y = s[i][1]; pv.z = s[i][2]; pv.w = s[i][3];
            *reinterpret_cast<float4*>(&Ps[(ty*4 + i)*PSTRIDE + tx*4]) = pv;
        }
        __syncthreads();

        #pragma unroll 4
        for (int j = 0; j < 64; ++j) {
            const float4 va = *reinterpret_cast<const float4*>(&Vs[j*QSTRIDE + tx*4]);
            const float4 vb = *reinterpret_cast<const float4*>(&Vs[j*QSTRIDE + 64 + tx*4]);
            #pragma unroll
            for (int i = 0; i < 4; i++) {
                const float p = Ps[(ty*4 + i)*PSTRIDE + j];
                o[i][0] = fmaf(p, va.x, o[i][0]);
                o[i][1] = fmaf(p, va.y, o[i][1]);
                o[i][2] = fmaf(p, va.z, o[i][2]);
                o[i][3] = fmaf(p, va.w, o[i][3]);
                o[i][4] = fmaf(p, vb.x, o[i][4]);
                o[i][5] = fmaf(p, vb.y, o[i][5]);
                o[i][6] = fmaf(p, vb.z, o[i][6]);
                o[i][7] = fmaf(p, vb.w, o[i][7]);
            }
        }
    }

    #pragma unroll
    for (int i = 0; i < 4; i++) {
        const float inv = 1.0f / l[i];
        const size_t r = rowbase + qb*64 + ty*4 + i;
        __half hh[8], ll[8];
        #pragma unroll
        for (int c = 0; c < 8; c++) split_val(o[i][c] * inv, hh[c], ll[c]);
        __half2* oh0 = reinterpret_cast<__half2*>(&Ohi[r*HID + colbase + tx*4]);
        __half2* ol0 = reinterpret_cast<__half2*>(&Olo[r*HID + colbase + tx*4]);
        oh0[0] = __halves2half2(hh[0], hh[1]);  oh0[1] = __halves2half2(hh[2], hh[3]);
        ol0[0] = __halves2half2(ll[0], ll[1]);  ol0[1] = __halves2half2(ll[2], ll[3]);
        __half2* oh1 = reinterpret_cast<__half2*>(&Ohi[r*HID + colbase + 64 + tx*4]);
        __half2* ol1 = reinterpret_cast<__half2*>(&Olo[r*HID + colbase + 64 + tx*4]);
        oh1[0] = __halves2half2(hh[4], hh[5]);  oh1[1] = __halves2half2(hh[6], hh[7]);
        ol1[0] = __halves2half2(ll[4], ll[5]);  ol1[1] = __halves2half2(ll[6], ll[7]);
    }
}

// ============================ host side =====================================
extern "C" void kernel_launch(void* const* d_in, const int* in_sizes, int n_in,
                              void* d_out, int out_size)
{
    const float* x     = (const float*)d_in[0];
    const float* wq    = (const float*)d_in[2];
    const float* wk    = (const float*)d_in[3];
    const float* wv    = (const float*)d_in[4];
    const float* wo    = (const float*)d_in[5];
    const float* w_in  = (const float*)d_in[6];
    const float* w_out = (const float*)d_in[7];
    const float* ln1_g = (const float*)d_in[8];
    const float* ln1_b = (const float*)d_in[9];
    const float* ln2_g = (const float*)d_in[10];
    const float* ln2_b = (const float*)d_in[11];
    float* out = (float*)d_out;

    float *q, *k, *v, *h;
    __half *xnh,*xnl,*atth,*attl,*hnh,*hnl,*ffh,*ffl;
    __half *wqh,*wql,*wkh,*wkl,*wvh,*wvl,*woh,*wol,*winh,*winl,*wouth,*woutl;
    cudaGetSymbolAddress((void**)&q,  g_q);
    cudaGetSymbolAddress((void**)&k,  g_k);
    cudaGetSymbolAddress((void**)&v,  g_v);
    cudaGetSymbolAddress((void**)&h,  g_h);
    cudaGetSymbolAddress((void**)&xnh, g_xnh);   cudaGetSymbolAddress((void**)&xnl, g_xnl);
    cudaGetSymbolAddress((void**)&atth, g_atth); cudaGetSymbolAddress((void**)&attl, g_attl);
    cudaGetSymbolAddress((void**)&hnh, g_hnh);   cudaGetSymbolAddress((void**)&hnl, g_hnl);
    cudaGetSymbolAddress((void**)&ffh, g_ffh);   cudaGetSymbolAddress((void**)&ffl, g_ffl);
    cudaGetSymbolAddress((void**)&wqh, g_wqh);   cudaGetSymbolAddress((void**)&wql, g_wql);
    cudaGetSymbolAddress((void**)&wkh, g_wkh);   cudaGetSymbolAddress((void**)&wkl, g_wkl);
    cudaGetSymbolAddress((void**)&wvh, g_wvh);   cudaGetSymbolAddress((void**)&wvl, g_wvl);
    cudaGetSymbolAddress((void**)&woh, g_woh);   cudaGetSymbolAddress((void**)&wol, g_wol);
    cudaGetSymbolAddress((void**)&winh, g_winh); cudaGetSymbolAddress((void**)&winl, g_winl);
    cudaGetSymbolAddress((void**)&wouth, g_wouth); cudaGetSymbolAddress((void**)&woutl, g_woutl);

    cudaFuncSetAttribute(tc_gemm<0>, cudaFuncAttributeMaxDynamicSharedMemorySize, GEMM_SMEM);
    cudaFuncSetAttribute(tc_gemm<1>, cudaFuncAttributeMaxDynamicSharedMemorySize, GEMM_SMEM);
    cudaFuncSetAttribute(tc_gemm<2>, cudaFuncAttributeMaxDynamicSharedMemorySize, GEMM_SMEM);
    const int smem_flash = (64*QSTRIDE + 128*KSTRIDE + 64*QSTRIDE + 64*PSTRIDE) * 4;
    cudaFuncSetAttribute(flash_kernel, cudaFuncAttributeMaxDynamicSharedMemorySize, smem_flash);

    {
        const int t = 256;
        dim3 g4((HID*HID/4 + t-1)/t, 4);
        split4_kernel<<<g4, t>>>(wq, wqh, wql, wk, wkh, wkl,
                                 wv, wvh, wvl, wo, woh, wol, HID*HID/4);
        dim3 g2((HID*FFD/4 + t-1)/t, 2);
        split2_kernel<<<g2, t>>>(w_in, winh, winl, w_out, wouth, woutl, HID*FFD/4);
    }

    ln_kernel<<<ROWS, 256>>>(x, ln1_g, ln1_b, xnh, xnl);

    dim3 gproj(HID/BN, ROWS/BM);
    tc_gemm<0><<<gproj, 256, GEMM_SMEM>>>(xnh, xnl, wqh, wql, nullptr, q, nullptr, nullptr, HID, HID);
    tc_gemm<0><<<gproj, 256, GEMM_SMEM>>>(xnh, xnl, wkh, wkl, nullptr, k, nullptr, nullptr, HID, HID);
    tc_gemm<0><<<gproj, 256, GEMM_SMEM>>>(xnh, xnl, wvh, wvl, nullptr, v, nullptr, nullptr, HID, HID);

    dim3 gattn(SEQ/64, BATCH*NHEAD);
    flash_kernel<<<gattn, 256, smem_flash>>>(q, k, v, atth, attl);

    tc_gemm<1><<<gproj, 256, GEMM_SMEM>>>(atth, attl, woh, wol, x, h, nullptr, nullptr, HID, HID);

    ln_kernel<<<ROWS, 256>>>(h, ln2_g, ln2_b, hnh, hnl);

    dim3 gff1(FFD/BN, ROWS/BM);
    tc_gemm<2><<<gff1, 256, GEMM_SMEM>>>(hnh, hnl, winh, winl, nullptr, nullptr, ffh, ffl, FFD, HID);

    dim3 gff2(HID/BN, ROWS/BM);
    tc_gemm<1><<<gff2, 256, GEMM_SMEM>>>(ffh, ffl, wouth, woutl, h, out, nullptr, nullptr, HID, FFD);
}

// round 7
// speedup vs baseline: 1.1457x; 1.1457x over previous
#include <cuda_runtime.h>
#include <cuda_fp16.h>
#include <math.h>
#include <cstdint>

#define BATCH 2
#define SEQ   2048
#define HID   2048
#define NHEAD 16
#define HDIM  128
#define FFD   8192
#define ROWS  (BATCH*SEQ)   // 4096
#define QKVLD (3*HID)       // 6144

// ---------------- scratch ---------------------------------------------------
__device__ float g_qkv[(size_t)ROWS*QKVLD];   // packed q|k|v
__device__ float g_h [ROWS*HID];
__device__ __half g_xnh[ROWS*HID];
__device__ __half g_xnl[ROWS*HID];
__device__ __half g_atth[ROWS*HID];
__device__ __half g_attl[ROWS*HID];
__device__ __half g_hnh[ROWS*HID];
__device__ __half g_hnl[ROWS*HID];
__device__ __half g_ffh[(size_t)ROWS*FFD];
__device__ __half g_ffl[(size_t)ROWS*FFD];
__device__ __half g_wqkvh[(size_t)HID*QKVLD];  // packed [K=HID][6144]
__device__ __half g_wqkvl[(size_t)HID*QKVLD];
__device__ __half g_woh[HID*HID];   __device__ __half g_wol[HID*HID];
__device__ __half g_winh[(size_t)HID*FFD];  __device__ __half g_winl[(size_t)HID*FFD];
__device__ __half g_wouth[(size_t)HID*FFD]; __device__ __half g_woutl[(size_t)HID*FFD];

// ============================ helpers ========================================
__device__ __forceinline__ uint32_t smem_u32(const void* p) {
    uint32_t a;
    asm("{ .reg .u64 t; cvta.to.shared.u64 t, %1; cvt.u32.u64 %0, t; }"
        : "=r"(a) : "l"(p));
    return a;
}
__device__ __forceinline__ void cp16(uint32_t dst, const void* src) {
    asm volatile("cp.async.cg.shared.global [%0], [%1], 16;" :: "r"(dst), "l"(src));
}
__device__ __forceinline__ void cp_commit() { asm volatile("cp.async.commit_group;"); }
template<int N> __device__ __forceinline__ void cp_wait() {
    asm volatile("cp.async.wait_group %0;" :: "n"(N));
}
__device__ __forceinline__ void ldsm_x4(uint32_t* r, uint32_t addr) {
    asm volatile("ldmatrix.sync.aligned.m8n8.x4.shared.b16 {%0,%1,%2,%3}, [%4];"
        : "=r"(r[0]), "=r"(r[1]), "=r"(r[2]), "=r"(r[3]) : "r"(addr));
}
__device__ __forceinline__ void ldsm_x4_t(uint32_t* r, uint32_t addr) {
    asm volatile("ldmatrix.sync.aligned.m8n8.x4.trans.shared.b16 {%0,%1,%2,%3}, [%4];"
        : "=r"(r[0]), "=r"(r[1]), "=r"(r[2]), "=r"(r[3]) : "r"(addr));
}
__device__ __forceinline__ void mma_f16(float* c, const uint32_t* a, const uint32_t* b) {
    asm volatile("mma.sync.aligned.m16n8k16.row.col.f32.f16.f16.f32 "
        "{%0,%1,%2,%3}, {%4,%5,%6,%7}, {%8,%9}, {%0,%1,%2,%3};"
        : "+f"(c[0]), "+f"(c[1]), "+f"(c[2]), "+f"(c[3])
        : "r"(a[0]), "r"(a[1]), "r"(a[2]), "r"(a[3]), "r"(b[0]), "r"(b[1]));
}
__device__ __forceinline__ float gelu_tanh(float x) {
    float x3 = x * x * x;
    float t  = tanhf(0.7978845608028654f * (x + 0.044715f * x3));
    return 0.5f * x * (1.0f + t);
}
__device__ __forceinline__ void split_val(float v, __half& hi, __half& lo) {
    hi = __float2half_rn(v);
    lo = __float2half_rn(v - __half2float(hi));
}

// ============================================================================
// split-fp16 tensor-core GEMM (3-term): C = Ahi*Bhi + Ahi*Blo + Alo*Bhi
// Round-4 configuration (measured best), pinned to 2 CTAs/SM.
// ============================================================================
#define BM 128
#define BN 128
#define BKH 32
#define LDAH 40
#define LDBH 136
#define ASZH (BM*LDAH)
#define BSZH (BKH*LDBH)
#define STG 3
#define STAGEH (2*ASZH + 2*BSZH)
#define GEMM_SMEM (STG*STAGEH*2)    // 113664 bytes -> 2 CTAs/SM

template<int ACT>
__global__ __launch_bounds__(256, 2) void tc_gemm(
    const __half* __restrict__ Ahi, const __half* __restrict__ Alo,
    const __half* __restrict__ Bhi, const __half* __restrict__ Blo,
    const float* __restrict__ Res, float* __restrict__ Cf,
    __half* __restrict__ Chi, __half* __restrict__ Clo,
    int N_, int K)
{
    extern __shared__ __align__(16) __half smem[];

    const int tid  = threadIdx.x;
    const int wid  = tid >> 5;
    const int lane = tid & 31;
    const int gid  = lane >> 2;
    const int tg   = lane & 3;
    const int wm   = wid & 3;
    const int wn   = wid >> 2;
    const int bm = blockIdx.y * BM;
    const int bn = blockIdx.x * BN;
    const int nK = K / BKH;

    const int a_m = lane & 15;
    const int a_k = (lane >> 4) * 8;
    const int b_k = ((lane >> 3) & 1) * 8 + (lane & 7);
    const int b_n = (lane >> 4) * 8;

    auto load_stage = [&](int s, int kt) {
        const int k0 = kt * BKH;
        __half* Ah = smem + s*STAGEH;
        __half* Al = Ah + ASZH;
        __half* Bh = Al + ASZH;
        __half* Bl = Bh + BSZH;
        #pragma unroll
        for (int i = 0; i < 2; i++) {
            const int c  = tid + 256*i;
            const int ar = c >> 2, ak = (c & 3) << 3;
            cp16(smem_u32(&Ah[ar*LDAH + ak]), &Ahi[(size_t)(bm + ar)*K + k0 + ak]);
            cp16(smem_u32(&Al[ar*LDAH + ak]), &Alo[(size_t)(bm + ar)*K + k0 + ak]);
            const int bk = c >> 4, bnn = (c & 15) << 3;
            cp16(smem_u32(&Bh[bk*LDBH + bnn]), &Bhi[(size_t)(k0 + bk)*N_ + bn + bnn]);
            cp16(smem_u32(&Bl[bk*LDBH + bnn]), &Blo[(size_t)(k0 + bk)*N_ + bn + bnn]);
        }
        cp_commit();
    };

    float acc[2][8][4];
    #pragma unroll
    for (int mt = 0; mt < 2; mt++)
        #pragma unroll
        for (int nt = 0; nt < 8; nt++)
            #pragma unroll
            for (int r = 0; r < 4; r++) acc[mt][nt][r] = 0.0f;

    load_stage(0, 0);
    load_stage(1, 1);

    for (int kt = 0; kt < nK; kt++) {
        cp_wait<1>();
        __syncthreads();
        const int s = kt % STG;
        const __half* Ah = smem + s*STAGEH;
        const __half* Al = Ah + ASZH;
        const __half* Bh = Al + ASZH;
        const __half* Bl = Bh + BSZH;

        #pragma unroll
        for (int kk = 0; kk < 2; kk++) {
            uint32_t ah[2][4], al[2][4];
            #pragma unroll
            for (int mt = 0; mt < 2; mt++) {
                const int mrow = wm*32 + mt*16 + a_m;
                const int koff = kk*16 + a_k;
                ldsm_x4(ah[mt], smem_u32(&Ah[mrow*LDAH + koff]));
                ldsm_x4(al[mt], smem_u32(&Al[mrow*LDAH + koff]));
            }
            uint32_t bh[4][4], bl[4][4];
            #pragma unroll
            for (int ng = 0; ng < 4; ng++) {
                const int koff = kk*16 + b_k;
                const int noff = wn*64 + ng*16 + b_n;
                ldsm_x4_t(bh[ng], smem_u32(&Bh[koff*LDBH + noff]));
                ldsm_x4_t(bl[ng], smem_u32(&Bl[koff*LDBH + noff]));
            }
            #pragma unroll
            for (int mt = 0; mt < 2; mt++)
                #pragma unroll
                for (int nt = 0; nt < 8; nt++) {
                    const uint32_t* bhp = &bh[nt >> 1][(nt & 1) * 2];
                    const uint32_t* blp = &bl[nt >> 1][(nt & 1) * 2];
                    mma_f16(acc[mt][nt], ah[mt], bhp);
                    mma_f16(acc[mt][nt], ah[mt], blp);
                    mma_f16(acc[mt][nt], al[mt], bhp);
                }
        }
        __syncthreads();
        if (kt + STG - 1 < nK)
            load_stage((kt + STG - 1) % STG, kt + STG - 1);
    }

    #pragma unroll
    for (int mt = 0; mt < 2; mt++) {
        #pragma unroll
        for (int half_ = 0; half_ < 2; half_++) {
            const int r = bm + wm*32 + mt*16 + gid + half_*8;
            #pragma unroll
            for (int nt = 0; nt < 8; nt++) {
                const int cc = bn + wn*64 + nt*8 + tg*2;
                float v0 = acc[mt][nt][half_*2 + 0];
                float v1 = acc[mt][nt][half_*2 + 1];
                if (ACT == 2) {
                    v0 = gelu_tanh(v0); v1 = gelu_tanh(v1);
                    __half h0, l0, h1, l1;
                    split_val(v0, h0, l0); split_val(v1, h1, l1);
                    *reinterpret_cast<__half2*>(&Chi[(size_t)r*N_ + cc]) = __halves2half2(h0, h1);
                    *reinterpret_cast<__half2*>(&Clo[(size_t)r*N_ + cc]) = __halves2half2(l0, l1);
                } else {
                    if (ACT == 1) {
                        const float2 rr = *reinterpret_cast<const float2*>(&Res[(size_t)r*N_ + cc]);
                        v0 += rr.x; v1 += rr.y;
                    }
                    float2 o; o.x = v0; o.y = v1;
                    *reinterpret_cast<float2*>(&Cf[(size_t)r*N_ + cc]) = o;
                }
            }
        }
    }
}

// ------------- weight splits -------------------------------------------------
// wq/wk/wv -> packed [HID][6144] at column offsets 0/2048/4096; wo -> [HID][HID]
__global__ void splitqkv_kernel(const float* __restrict__ wq,
                                const float* __restrict__ wk,
                                const float* __restrict__ wv,
                                const float* __restrict__ wo,
                                __half* __restrict__ qkvh, __half* __restrict__ qkvl,
                                __half* __restrict__ woh,  __half* __restrict__ wol,
                                int n4)
{
    const int i = blockIdx.x*blockDim.x + threadIdx.x;
    if (i >= n4) return;
    const int y = blockIdx.y;
    const float* in = (y == 0) ? wq : (y == 1) ? wk : (y == 2) ? wv : wo;
    const int e   = i * 4;
    const int row = e >> 11;          // /2048
    const int col = e & 2047;
    float4 v = reinterpret_cast<const float4*>(in)[i];
    __half a0,b0,a1,b1,a2,b2,a3,b3;
    split_val(v.x, a0, b0); split_val(v.y, a1, b1);
    split_val(v.z, a2, b2); split_val(v.w, a3, b3);
    __half *hi, *lo; size_t o;
    if (y < 3) { hi = qkvh; lo = qkvl; o = (size_t)row*QKVLD + y*HID + col; }
    else       { hi = woh;  lo = wol;  o = (size_t)row*HID + col; }
    reinterpret_cast<__half2*>(hi + o)[0] = __halves2half2(a0, a1);
    reinterpret_cast<__half2*>(hi + o)[1] = __halves2half2(a2, a3);
    reinterpret_cast<__half2*>(lo + o)[0] = __halves2half2(b0, b1);
    reinterpret_cast<__half2*>(lo + o)[1] = __halves2half2(b2, b3);
}
__global__ void split2_kernel(const float* __restrict__ w0, __half* h0, __half* l0,
                              const float* __restrict__ w1, __half* h1, __half* l1,
                              int n4)
{
    const float* in = blockIdx.y ? w1 : w0;
    __half* hi = blockIdx.y ? h1 : h0;
    __half* lo = blockIdx.y ? l1 : l0;
    const int i = blockIdx.x*blockDim.x + threadIdx.x;
    if (i >= n4) return;
    float4 v = reinterpret_cast<const float4*>(in)[i];
    __half a0,b0,a1,b1,a2,b2,a3,b3;
    split_val(v.x, a0, b0); split_val(v.y, a1, b1);
    split_val(v.z, a2, b2); split_val(v.w, a3, b3);
    reinterpret_cast<__half2*>(hi)[2*i+0] = __halves2half2(a0, a1);
    reinterpret_cast<__half2*>(hi)[2*i+1] = __halves2half2(a2, a3);
    reinterpret_cast<__half2*>(lo)[2*i+0] = __halves2half2(b0, b1);
    reinterpret_cast<__half2*>(lo)[2*i+1] = __halves2half2(b2, b3);
}

// ---------------- LayerNorm -> split fp16 outputs ---------------------------
__global__ void ln_kernel(const float* __restrict__ x,
                          const float* __restrict__ g,
                          const float* __restrict__ b,
                          __half* __restrict__ ohi, __half* __restrict__ olo)
{
    const int row = blockIdx.x;
    const int tid = threadIdx.x;
    const float* xr = x + (size_t)row * HID;

    float4 v0 = reinterpret_cast<const float4*>(xr)[tid];
    float4 v1 = reinterpret_cast<const float4*>(xr)[tid + 256];

    __shared__ float red[8];

    float s = v0.x+v0.y+v0.z+v0.w + v1.x+v1.y+v1.z+v1.w;
    #pragma unroll
    for (int o = 16; o > 0; o >>= 1) s += __shfl_xor_sync(0xffffffffu, s, o);
    if ((tid & 31) == 0) red[tid >> 5] = s;
    __syncthreads();
    float mu = (red[0]+red[1]+red[2]+red[3]+red[4]+red[5]+red[6]+red[7]) * (1.0f/HID);
    __syncthreads();

    float d0x=v0.x-mu, d0y=v0.y-mu, d0z=v0.z-mu, d0w=v0.w-mu;
    float d1x=v1.x-mu, d1y=v1.y-mu, d1z=v1.z-mu, d1w=v1.w-mu;
    float sq = d0x*d0x+d0y*d0y+d0z*d0z+d0w*d0w + d1x*d1x+d1y*d1y+d1z*d1z+d1w*d1w;
    #pragma unroll
    for (int o = 16; o > 0; o >>= 1) sq += __shfl_xor_sync(0xffffffffu, sq, o);
    if ((tid & 31) == 0) red[tid >> 5] = sq;
    __syncthreads();
    float var = (red[0]+red[1]+red[2]+red[3]+red[4]+red[5]+red[6]+red[7]) * (1.0f/HID);
    float rstd = rsqrtf(var + 1e-5f);

    float4 g0 = reinterpret_cast<const float4*>(g)[tid];
    float4 g1 = reinterpret_cast<const float4*>(g)[tid + 256];
    float4 b0 = reinterpret_cast<const float4*>(b)[tid];
    float4 b1 = reinterpret_cast<const float4*>(b)[tid + 256];

    float o0[4] = { d0x*rstd*g0.x + b0.x, d0y*rstd*g0.y + b0.y,
                    d0z*rstd*g0.z + b0.z, d0w*rstd*g0.w + b0.w };
    float o1[4] = { d1x*rstd*g1.x + b1.x, d1y*rstd*g1.y + b1.y,
                    d1z*rstd*g1.z + b1.z, d1w*rstd*g1.w + b1.w };

    const size_t base = (size_t)row * HID;
    __half h[4], l[4];
    #pragma unroll
    for (int j = 0; j < 4; j++) split_val(o0[j], h[j], l[j]);
    reinterpret_cast<__half2*>(ohi + base)[tid*2+0] = __halves2half2(h[0], h[1]);
    reinterpret_cast<__half2*>(ohi + base)[tid*2+1] = __halves2half2(h[2], h[3]);
    reinterpret_cast<__half2*>(olo + base)[tid*2+0] = __halves2half2(l[0], l[1]);
    reinterpret_cast<__half2*>(olo + base)[tid*2+1] = __halves2half2(l[2], l[3]);
    #pragma unroll
    for (int j = 0; j < 4; j++) split_val(o1[j], h[j], l[j]);
    reinterpret_cast<__half2*>(ohi + base)[(tid+256)*2+0] = __halves2half2(h[0], h[1]);
    reinterpret_cast<__half2*>(ohi + base)[(tid+256)*2+1] = __halves2half2(h[2], h[3]);
    reinterpret_cast<__half2*>(olo + base)[(tid+256)*2+0] = __halves2half2(l[0], l[1]);
    reinterpret_cast<__half2*>(olo + base)[(tid+256)*2+1] = __halves2half2(l[2], l[3]);
}

// ---------------- Flash attention (causal, fp32, packed QKV) ----------------
#define QSTRIDE 132
#define KSTRIDE 68
#define PSTRIDE 68

__global__ __launch_bounds__(256) void flash_kernel(
    const float* __restrict__ QKV,
    __half* __restrict__ Ohi, __half* __restrict__ Olo)
{
    extern __shared__ float sm[];
    float* Qs = sm;
    float* Kt = Qs + 64*QSTRIDE;
    float* Vs = Kt + 128*KSTRIDE;
    float* Ps = Vs + 64*QSTRIDE;

    const int tid = threadIdx.x;
    const int tx = tid & 15;
    const int ty = tid >> 4;
    const int bh = blockIdx.y;
    const int b  = bh >> 4;
    const int h  = bh & 15;
    const int qb = blockIdx.x;
    const size_t rowbase = (size_t)b * SEQ;
    const int colbase = h * HDIM;
    const float scale = 0.088388347648318447f;

    #pragma unroll
    for (int it = 0; it < 8; ++it) {
        int idx = it * 256 + tid;
        int r  = idx >> 5;
        int c4 = (idx & 31) << 2;
        float4 qv = *reinterpret_cast<const float4*>(
            &QKV[(rowbase + qb*64 + r) * QKVLD + colbase + c4]);
        *reinterpret_cast<float4*>(&Qs[r*QSTRIDE + c4]) = qv;
    }

    float m[4], l[4], o[4][8];
    #pragma unroll
    for (int i = 0; i < 4; i++) {
        m[i] = -1e30f; l[i] = 0.0f;
        #pragma unroll
        for (int c = 0; c < 8; c++) o[i][c] = 0.0f;
    }

    for (int kb = 0; kb <= qb; ++kb) {
        __syncthreads();
        #pragma unroll
        for (int it = 0; it < 8; ++it) {
            int idx = it * 256 + tid;
            int r  = idx >> 5;
            int c4 = (idx & 31) << 2;
            const size_t grow = (rowbase + kb*64 + r) * (size_t)QKVLD + colbase + c4;
            float4 kv = *reinterpret_cast<const float4*>(&QKV[grow + HID]);
            Kt[(c4+0)*KSTRIDE + r] = kv.x;
            Kt[(c4+1)*KSTRIDE + r] = kv.y;
            Kt[(c4+2)*KSTRIDE + r] = kv.z;
            Kt[(c4+3)*KSTRIDE + r] = kv.w;
            float4 vv = *reinterpret_cast<const float4*>(&QKV[grow + 2*HID]);
            *reinterpret_cast<float4*>(&Vs[r*QSTRIDE + c4]) = vv;
        }
        __syncthreads();

        float s[4][4];
        #pragma unroll
        for (int i = 0; i < 4; i++)
            #pragma unroll
            for (int jj = 0; jj < 4; jj++) s[i][jj] = 0.0f;

        #pragma unroll 4
        for (int d = 0; d < HDIM; ++d) {
            const float4 kr = *reinterpret_cast<const float4*>(&Kt[d*KSTRIDE + tx*4]);
            #pragma unroll
            for (int i = 0; i < 4; i++) {
                const float qv = Qs[(ty*4 + i)*QSTRIDE + d];
                s[i][0] = fmaf(qv, kr.x, s[i][0]);
                s[i][1] = fmaf(qv, kr.y, s[i][1]);
                s[i][2] = fmaf(qv, kr.z, s[i][2]);
                s[i][3] = fmaf(qv, kr.w, s[i][3]);
            }
        }

        const bool diag = (kb == qb);
        #pragma unroll
        for (int i = 0; i < 4; i++) {
            const int qg = qb*64 + ty*4 + i;
            float mx = -1e30f;
            #pragma unroll
            for (int jj = 0; jj < 4; jj++) {
                float v = s[i][jj] * scale;
                if (diag && (kb*64 + tx*4 + jj) > qg) v = -1e30f;
                s[i][jj] = v;
                mx = fmaxf(mx, v);
            }
            #pragma unroll
            for (int off = 8; off > 0; off >>= 1)
                mx = fmaxf(mx, __shfl_xor_sync(0xffffffffu, mx, off));
            float mnew = fmaxf(m[i], mx);
            float corr = __expf(m[i] - mnew);
            float rs = 0.0f;
            #pragma unroll
            for (int jj = 0; jj < 4; jj++) {
                float p = __expf(s[i][jj] - mnew);
                s[i][jj] = p;
                rs += p;
            }
            #pragma unroll
            for (int off = 8; off > 0; off >>= 1)
                rs += __shfl_xor_sync(0xffffffffu, rs, off);
            l[i] = l[i]*corr + rs;
            m[i] = mnew;
            #pragma unroll
            for (int c = 0; c < 8; c++) o[i][c] *= corr;
            float4 pv; pv.x = s[i][0]; pv.y = s[i][1]; pv.z = s[i][2]; pv.w = s[i][3];
            *reinterpret_cast<float4*>(&Ps[(ty*4 + i)*PSTRIDE + tx*4]) = pv;
        }
        __syncthreads();

        #pragma unroll 4
        for (int j = 0; j < 64; ++j) {
            const float4 va = *reinterpret_cast<const float4*>(&Vs[j*QSTRIDE + tx*4]);
            const float4 vb = *reinterpret_cast<const float4*>(&Vs[j*QSTRIDE + 64 + tx*4]);
            #pragma unroll
            for (int i = 0; i < 4; i++) {
                const float p = Ps[(ty*4 + i)*PSTRIDE + j];
                o[i][0] = fmaf(p, va.x, o[i][0]);
                o[i][1] = fmaf(p, va.y, o[i][1]);
                o[i][2] = fmaf(p, va.z, o[i][2]);
                o[i][3] = fmaf(p, va.w, o[i][3]);
                o[i][4] = fmaf(p, vb.x, o[i][4]);
                o[i][5] = fmaf(p, vb.y, o[i][5]);
                o[i][6] = fmaf(p, vb.z, o[i][6]);
                o[i][7] = fmaf(p, vb.w, o[i][7]);
            }
        }
    }

    #pragma unroll
    for (int i = 0; i < 4; i++) {
        const float inv = 1.0f / l[i];
        const size_t r = rowbase + qb*64 + ty*4 + i;
        __half hh[8], ll[8];
        #pragma unroll
        for (int c = 0; c < 8; c++) split_val(o[i][c] * inv, hh[c], ll[c]);
        __half2* oh0 = reinterpret_cast<__half2*>(&Ohi[r*HID + colbase + tx*4]);
        __half2* ol0 = reinterpret_cast<__half2*>(&Olo[r*HID + colbase + tx*4]);
        oh0[0] = __halves2half2(hh[0], hh[1]);  oh0[1] = __halves2half2(hh[2], hh[3]);
        ol0[0] = __halves2half2(ll[0], ll[1]);  ol0[1] = __halves2half2(ll[2], ll[3]);
        __half2* oh1 = reinterpret_cast<__half2*>(&Ohi[r*HID + colbase + 64 + tx*4]);
        __half2* ol1 = reinterpret_cast<__half2*>(&Olo[r*HID + colbase + 64 + tx*4]);
        oh1[0] = __halves2half2(hh[4], hh[5]);  oh1[1] = __halves2half2(hh[6], hh[7]);
        ol1[0] = __halves2half2(ll[4], ll[5]);  ol1[1] = __halves2half2(ll[6], ll[7]);
    }
}

// ============================ host side =====================================
extern "C" void kernel_launch(void* const* d_in, const int* in_sizes, int n_in,
                              void* d_out, int out_size)
{
    const float* x     = (const float*)d_in[0];
    const float* wq    = (const float*)d_in[2];
    const float* wk    = (const float*)d_in[3];
    const float* wv    = (const float*)d_in[4];
    const float* wo    = (const float*)d_in[5];
    const float* w_in  = (const float*)d_in[6];
    const float* w_out = (const float*)d_in[7];
    const float* ln1_g = (const float*)d_in[8];
    const float* ln1_b = (const float*)d_in[9];
    const float* ln2_g = (const float*)d_in[10];
    const float* ln2_b = (const float*)d_in[11];
    float* out = (float*)d_out;

    float *qkv, *h;
    __half *xnh,*xnl,*atth,*attl,*hnh,*hnl,*ffh,*ffl;
    __half *wqkvh,*wqkvl,*woh,*wol,*winh,*winl,*wouth,*woutl;
    cudaGetSymbolAddress((void**)&qkv, g_qkv);
    cudaGetSymbolAddress((void**)&h,  g_h);
    cudaGetSymbolAddress((void**)&xnh, g_xnh);   cudaGetSymbolAddress((void**)&xnl, g_xnl);
    cudaGetSymbolAddress((void**)&atth, g_atth); cudaGetSymbolAddress((void**)&attl, g_attl);
    cudaGetSymbolAddress((void**)&hnh, g_hnh);   cudaGetSymbolAddress((void**)&hnl, g_hnl);
    cudaGetSymbolAddress((void**)&ffh, g_ffh);   cudaGetSymbolAddress((void**)&ffl, g_ffl);
    cudaGetSymbolAddress((void**)&wqkvh, g_wqkvh); cudaGetSymbolAddress((void**)&wqkvl, g_wqkvl);
    cudaGetSymbolAddress((void**)&woh, g_woh);   cudaGetSymbolAddress((void**)&wol, g_wol);
    cudaGetSymbolAddress((void**)&winh, g_winh); cudaGetSymbolAddress((void**)&winl, g_winl);
    cudaGetSymbolAddress((void**)&wouth, g_wouth); cudaGetSymbolAddress((void**)&woutl, g_woutl);

    cudaFuncSetAttribute(tc_gemm<0>, cudaFuncAttributeMaxDynamicSharedMemorySize, GEMM_SMEM);
    cudaFuncSetAttribute(tc_gemm<1>, cudaFuncAttributeMaxDynamicSharedMemorySize, GEMM_SMEM);
    cudaFuncSetAttribute(tc_gemm<2>, cudaFuncAttributeMaxDynamicSharedMemorySize, GEMM_SMEM);
    const int smem_flash = (64*QSTRIDE + 128*KSTRIDE + 64*QSTRIDE + 64*PSTRIDE) * 4;
    cudaFuncSetAttribute(flash_kernel, cudaFuncAttributeMaxDynamicSharedMemorySize, smem_flash);

    // 0. split weights
    {
        const int t = 256;
        dim3 gq((HID*HID/4 + t-1)/t, 4);
        splitqkv_kernel<<<gq, t>>>(wq, wk, wv, wo, wqkvh, wqkvl, woh, wol, HID*HID/4);
        dim3 g2((HID*FFD/4 + t-1)/t, 2);
        split2_kernel<<<g2, t>>>(w_in, winh, winl, w_out, wouth, woutl, HID*FFD/4);
    }

    // 1. LN1 -> split
    ln_kernel<<<ROWS, 256>>>(x, ln1_g, ln1_b, xnh, xnl);

    // 2. fused QKV projection (one GEMM, N=6144)
    dim3 gqkv(QKVLD/BN, ROWS/BM);
    tc_gemm<0><<<gqkv, 256, GEMM_SMEM>>>(xnh, xnl, wqkvh, wqkvl, nullptr, qkv,
                                         nullptr, nullptr, QKVLD, HID);

    // 3. causal flash attention on packed qkv -> split att
    dim3 gattn(SEQ/64, BATCH*NHEAD);
    flash_kernel<<<gattn, 256, smem_flash>>>(qkv, atth, attl);

    // 4. output projection + residual -> h (fp32)
    dim3 gproj(HID/BN, ROWS/BM);
    tc_gemm<1><<<gproj, 256, GEMM_SMEM>>>(atth, attl, woh, wol, x, h,
                                          nullptr, nullptr, HID, HID);

    // 5. LN2 -> split
    ln_kernel<<<ROWS, 256>>>(h, ln2_g, ln2_b, hnh, hnl);

    // 6. FFN up + GELU -> split ff
    dim3 gff1(FFD/BN, ROWS/BM);
    tc_gemm<2><<<gff1, 256, GEMM_SMEM>>>(hnh, hnl, winh, winl, nullptr, nullptr,
                                         ffh, ffl, FFD, HID);

    // 7. FFN down + residual -> d_out (fp32)
    dim3 gff2(HID/BN, ROWS/BM);
    tc_gemm<1><<<gff2, 256, GEMM_SMEM>>>(ffh, ffl, wouth, woutl, h, out,
                                         nullptr, nullptr, HID, FFD);
}

// round 8
// speedup vs baseline: 1.1611x; 1.0134x over previous
#include <cuda_runtime.h>
#include <cuda_fp16.h>
#include <math.h>
#include <cstdint>

#define BATCH 2
#define SEQ   2048
#define HID   2048
#define NHEAD 16
#define HDIM  128
#define FFD   8192
#define ROWS  (BATCH*SEQ)   // 4096
#define QKVLD (3*HID)       // 6144

// ---------------- scratch ---------------------------------------------------
__device__ float g_qkv[(size_t)ROWS*QKVLD];   // packed q|k|v
__device__ float g_h [ROWS*HID];
__device__ __half g_xnh[ROWS*HID];
__device__ __half g_xnl[ROWS*HID];
__device__ __half g_atth[ROWS*HID];
__device__ __half g_attl[ROWS*HID];
__device__ __half g_hnh[ROWS*HID];
__device__ __half g_hnl[ROWS*HID];
__device__ __half g_ffh[(size_t)ROWS*FFD];
__device__ __half g_ffl[(size_t)ROWS*FFD];
__device__ __half g_wqkvh[(size_t)HID*QKVLD];  // packed [K=HID][6144]
__device__ __half g_wqkvl[(size_t)HID*QKVLD];
__device__ __half g_woh[HID*HID];   __device__ __half g_wol[HID*HID];
__device__ __half g_winh[(size_t)HID*FFD];  __device__ __half g_winl[(size_t)HID*FFD];
__device__ __half g_wouth[(size_t)HID*FFD]; __device__ __half g_woutl[(size_t)HID*FFD];

// ============================ helpers ========================================
__device__ __forceinline__ uint32_t smem_u32(const void* p) {
    uint32_t a;
    asm("{ .reg .u64 t; cvta.to.shared.u64 t, %1; cvt.u32.u64 %0, t; }"
        : "=r"(a) : "l"(p));
    return a;
}
__device__ __forceinline__ void cp16(uint32_t dst, const void* src) {
    asm volatile("cp.async.cg.shared.global [%0], [%1], 16;" :: "r"(dst), "l"(src));
}
__device__ __forceinline__ void cp_commit() { asm volatile("cp.async.commit_group;"); }
template<int N> __device__ __forceinline__ void cp_wait() {
    asm volatile("cp.async.wait_group %0;" :: "n"(N));
}
__device__ __forceinline__ void ldsm_x4(uint32_t* r, uint32_t addr) {
    asm volatile("ldmatrix.sync.aligned.m8n8.x4.shared.b16 {%0,%1,%2,%3}, [%4];"
        : "=r"(r[0]), "=r"(r[1]), "=r"(r[2]), "=r"(r[3]) : "r"(addr));
}
__device__ __forceinline__ void ldsm_x4_t(uint32_t* r, uint32_t addr) {
    asm volatile("ldmatrix.sync.aligned.m8n8.x4.trans.shared.b16 {%0,%1,%2,%3}, [%4];"
        : "=r"(r[0]), "=r"(r[1]), "=r"(r[2]), "=r"(r[3]) : "r"(addr));
}
__device__ __forceinline__ void mma_f16(float* c, const uint32_t* a, const uint32_t* b) {
    asm volatile("mma.sync.aligned.m16n8k16.row.col.f32.f16.f16.f32 "
        "{%0,%1,%2,%3}, {%4,%5,%6,%7}, {%8,%9}, {%0,%1,%2,%3};"
        : "+f"(c[0]), "+f"(c[1]), "+f"(c[2]), "+f"(c[3])
        : "r"(a[0]), "r"(a[1]), "r"(a[2]), "r"(a[3]), "r"(b[0]), "r"(b[1]));
}
__device__ __forceinline__ float gelu_tanh(float x) {
    float x3 = x * x * x;
    float t  = tanhf(0.7978845608028654f * (x + 0.044715f * x3));
    return 0.5f * x * (1.0f + t);
}
__device__ __forceinline__ void split_val(float v, __half& hi, __half& lo) {
    hi = __float2half_rn(v);
    lo = __float2half_rn(v - __half2float(hi));
}

// ============================================================================
// split-fp16 tensor-core GEMM (3-term): C = Ahi*Bhi + Ahi*Blo + Alo*Bhi
// 2 CTAs/SM; ONE barrier per k-tile (refill of stage (kt+2)%3 is safe right
// after the barrier: its last readers finished at kt-1, proven by reg deps).
// ============================================================================
#define BM 128
#define BN 128
#define BKH 32
#define LDAH 40
#define LDBH 136
#define ASZH (BM*LDAH)
#define BSZH (BKH*LDBH)
#define STG 3
#define STAGEH (2*ASZH + 2*BSZH)
#define GEMM_SMEM (STG*STAGEH*2)    // 113664 bytes -> 2 CTAs/SM

template<int ACT>
__global__ __launch_bounds__(256, 2) void tc_gemm(
    const __half* __restrict__ Ahi, const __half* __restrict__ Alo,
    const __half* __restrict__ Bhi, const __half* __restrict__ Blo,
    const float* __restrict__ Res, float* __restrict__ Cf,
    __half* __restrict__ Chi, __half* __restrict__ Clo,
    int N_, int K)
{
    extern __shared__ __align__(16) __half smem[];

    const int tid  = threadIdx.x;
    const int wid  = tid >> 5;
    const int lane = tid & 31;
    const int gid  = lane >> 2;
    const int tg   = lane & 3;
    const int wm   = wid & 3;
    const int wn   = wid >> 2;
    const int bm = blockIdx.y * BM;
    const int bn = blockIdx.x * BN;
    const int nK = K / BKH;

    const int a_m = lane & 15;
    const int a_k = (lane >> 4) * 8;
    const int b_k = ((lane >> 3) & 1) * 8 + (lane & 7);
    const int b_n = (lane >> 4) * 8;

    auto load_stage = [&](int s, int kt) {
        const int k0 = kt * BKH;
        __half* Ah = smem + s*STAGEH;
        __half* Al = Ah + ASZH;
        __half* Bh = Al + ASZH;
        __half* Bl = Bh + BSZH;
        #pragma unroll
        for (int i = 0; i < 2; i++) {
            const int c  = tid + 256*i;
            const int ar = c >> 2, ak = (c & 3) << 3;
            cp16(smem_u32(&Ah[ar*LDAH + ak]), &Ahi[(size_t)(bm + ar)*K + k0 + ak]);
            cp16(smem_u32(&Al[ar*LDAH + ak]), &Alo[(size_t)(bm + ar)*K + k0 + ak]);
            const int bk = c >> 4, bnn = (c & 15) << 3;
            cp16(smem_u32(&Bh[bk*LDBH + bnn]), &Bhi[(size_t)(k0 + bk)*N_ + bn + bnn]);
            cp16(smem_u32(&Bl[bk*LDBH + bnn]), &Blo[(size_t)(k0 + bk)*N_ + bn + bnn]);
        }
        cp_commit();
    };

    float acc[2][8][4];
    #pragma unroll
    for (int mt = 0; mt < 2; mt++)
        #pragma unroll
        for (int nt = 0; nt < 8; nt++)
            #pragma unroll
            for (int r = 0; r < 4; r++) acc[mt][nt][r] = 0.0f;

    load_stage(0, 0);
    load_stage(1, 1);

    for (int kt = 0; kt < nK; kt++) {
        cp_wait<1>();
        __syncthreads();
        // refill early: targets stage (kt+2)%3 == (kt-1)%3, whose readers
        // completed before the barrier above.
        if (kt + STG - 1 < nK)
            load_stage((kt + STG - 1) % STG, kt + STG - 1);

        const int s = kt % STG;
        const __half* Ah = smem + s*STAGEH;
        const __half* Al = Ah + ASZH;
        const __half* Bh = Al + ASZH;
        const __half* Bl = Bh + BSZH;

        #pragma unroll
        for (int kk = 0; kk < 2; kk++) {
            uint32_t ah[2][4], al[2][4];
            #pragma unroll
            for (int mt = 0; mt < 2; mt++) {
                const int mrow = wm*32 + mt*16 + a_m;
                const int koff = kk*16 + a_k;
                ldsm_x4(ah[mt], smem_u32(&Ah[mrow*LDAH + koff]));
                ldsm_x4(al[mt], smem_u32(&Al[mrow*LDAH + koff]));
            }
            uint32_t bh[4][4], bl[4][4];
            #pragma unroll
            for (int ng = 0; ng < 4; ng++) {
                const int koff = kk*16 + b_k;
                const int noff = wn*64 + ng*16 + b_n;
                ldsm_x4_t(bh[ng], smem_u32(&Bh[koff*LDBH + noff]));
                ldsm_x4_t(bl[ng], smem_u32(&Bl[koff*LDBH + noff]));
            }
            #pragma unroll
            for (int mt = 0; mt < 2; mt++)
                #pragma unroll
                for (int nt = 0; nt < 8; nt++) {
                    const uint32_t* bhp = &bh[nt >> 1][(nt & 1) * 2];
                    const uint32_t* blp = &bl[nt >> 1][(nt & 1) * 2];
                    mma_f16(acc[mt][nt], ah[mt], bhp);
                    mma_f16(acc[mt][nt], ah[mt], blp);
                    mma_f16(acc[mt][nt], al[mt], bhp);
                }
        }
    }

    #pragma unroll
    for (int mt = 0; mt < 2; mt++) {
        #pragma unroll
        for (int half_ = 0; half_ < 2; half_++) {
            const int r = bm + wm*32 + mt*16 + gid + half_*8;
            #pragma unroll
            for (int nt = 0; nt < 8; nt++) {
                const int cc = bn + wn*64 + nt*8 + tg*2;
                float v0 = acc[mt][nt][half_*2 + 0];
                float v1 = acc[mt][nt][half_*2 + 1];
                if (ACT == 2) {
                    v0 = gelu_tanh(v0); v1 = gelu_tanh(v1);
                    __half h0, l0, h1, l1;
                    split_val(v0, h0, l0); split_val(v1, h1, l1);
                    *reinterpret_cast<__half2*>(&Chi[(size_t)r*N_ + cc]) = __halves2half2(h0, h1);
                    *reinterpret_cast<__half2*>(&Clo[(size_t)r*N_ + cc]) = __halves2half2(l0, l1);
                } else {
                    if (ACT == 1) {
                        const float2 rr = *reinterpret_cast<const float2*>(&Res[(size_t)r*N_ + cc]);
                        v0 += rr.x; v1 += rr.y;
                    }
                    float2 o; o.x = v0; o.y = v1;
                    *reinterpret_cast<float2*>(&Cf[(size_t)r*N_ + cc]) = o;
                }
            }
        }
    }
}

// ------------- weight splits -------------------------------------------------
__global__ void splitqkv_kernel(const float* __restrict__ wq,
                                const float* __restrict__ wk,
                                const float* __restrict__ wv,
                                const float* __restrict__ wo,
                                __half* __restrict__ qkvh, __half* __restrict__ qkvl,
                                __half* __restrict__ woh,  __half* __restrict__ wol,
                                int n4)
{
    const int i = blockIdx.x*blockDim.x + threadIdx.x;
    if (i >= n4) return;
    const int y = blockIdx.y;
    const float* in = (y == 0) ? wq : (y == 1) ? wk : (y == 2) ? wv : wo;
    const int e   = i * 4;
    const int row = e >> 11;
    const int col = e & 2047;
    float4 v = reinterpret_cast<const float4*>(in)[i];
    __half a0,b0,a1,b1,a2,b2,a3,b3;
    split_val(v.x, a0, b0); split_val(v.y, a1, b1);
    split_val(v.z, a2, b2); split_val(v.w, a3, b3);
    __half *hi, *lo; size_t o;
    if (y < 3) { hi = qkvh; lo = qkvl; o = (size_t)row*QKVLD + y*HID + col; }
    else       { hi = woh;  lo = wol;  o = (size_t)row*HID + col; }
    reinterpret_cast<__half2*>(hi + o)[0] = __halves2half2(a0, a1);
    reinterpret_cast<__half2*>(hi + o)[1] = __halves2half2(a2, a3);
    reinterpret_cast<__half2*>(lo + o)[0] = __halves2half2(b0, b1);
    reinterpret_cast<__half2*>(lo + o)[1] = __halves2half2(b2, b3);
}
__global__ void split2_kernel(const float* __restrict__ w0, __half* h0, __half* l0,
                              const float* __restrict__ w1, __half* h1, __half* l1,
                              int n4)
{
    const float* in = blockIdx.y ? w1 : w0;
    __half* hi = blockIdx.y ? h1 : h0;
    __half* lo = blockIdx.y ? l1 : l0;
    const int i = blockIdx.x*blockDim.x + threadIdx.x;
    if (i >= n4) return;
    float4 v = reinterpret_cast<const float4*>(in)[i];
    __half a0,b0,a1,b1,a2,b2,a3,b3;
    split_val(v.x, a0, b0); split_val(v.y, a1, b1);
    split_val(v.z, a2, b2); split_val(v.w, a3, b3);
    reinterpret_cast<__half2*>(hi)[2*i+0] = __halves2half2(a0, a1);
    reinterpret_cast<__half2*>(hi)[2*i+1] = __halves2half2(a2, a3);
    reinterpret_cast<__half2*>(lo)[2*i+0] = __halves2half2(b0, b1);
    reinterpret_cast<__half2*>(lo)[2*i+1] = __halves2half2(b2, b3);
}

// ---------------- LayerNorm -> split fp16 outputs ---------------------------
__global__ void ln_kernel(const float* __restrict__ x,
                          const float* __restrict__ g,
                          const float* __restrict__ b,
                          __half* __restrict__ ohi, __half* __restrict__ olo)
{
    const int row = blockIdx.x;
    const int tid = threadIdx.x;
    const float* xr = x + (size_t)row * HID;

    float4 v0 = reinterpret_cast<const float4*>(xr)[tid];
    float4 v1 = reinterpret_cast<const float4*>(xr)[tid + 256];

    __shared__ float red[8];

    float s = v0.x+v0.y+v0.z+v0.w + v1.x+v1.y+v1.z+v1.w;
    #pragma unroll
    for (int o = 16; o > 0; o >>= 1) s += __shfl_xor_sync(0xffffffffu, s, o);
    if ((tid & 31) == 0) red[tid >> 5] = s;
    __syncthreads();
    float mu = (red[0]+red[1]+red[2]+red[3]+red[4]+red[5]+red[6]+red[7]) * (1.0f/HID);
    __syncthreads();

    float d0x=v0.x-mu, d0y=v0.y-mu, d0z=v0.z-mu, d0w=v0.w-mu;
    float d1x=v1.x-mu, d1y=v1.y-mu, d1z=v1.z-mu, d1w=v1.w-mu;
    float sq = d0x*d0x+d0y*d0y+d0z*d0z+d0w*d0w + d1x*d1x+d1y*d1y+d1z*d1z+d1w*d1w;
    #pragma unroll
    for (int o = 16; o > 0; o >>= 1) sq += __shfl_xor_sync(0xffffffffu, sq, o);
    if ((tid & 31) == 0) red[tid >> 5] = sq;
    __syncthreads();
    float var = (red[0]+red[1]+red[2]+red[3]+red[4]+red[5]+red[6]+red[7]) * (1.0f/HID);
    float rstd = rsqrtf(var + 1e-5f);

    float4 g0 = reinterpret_cast<const float4*>(g)[tid];
    float4 g1 = reinterpret_cast<const float4*>(g)[tid + 256];
    float4 b0 = reinterpret_cast<const float4*>(b)[tid];
    float4 b1 = reinterpret_cast<const float4*>(b)[tid + 256];

    float o0[4] = { d0x*rstd*g0.x + b0.x, d0y*rstd*g0.y + b0.y,
                    d0z*rstd*g0.z + b0.z, d0w*rstd*g0.w + b0.w };
    float o1[4] = { d1x*rstd*g1.x + b1.x, d1y*rstd*g1.y + b1.y,
                    d1z*rstd*g1.z + b1.z, d1w*rstd*g1.w + b1.w };

    const size_t base = (size_t)row * HID;
    __half h[4], l[4];
    #pragma unroll
    for (int j = 0; j < 4; j++) split_val(o0[j], h[j], l[j]);
    reinterpret_cast<__half2*>(ohi + base)[tid*2+0] = __halves2half2(h[0], h[1]);
    reinterpret_cast<__half2*>(ohi + base)[tid*2+1] = __halves2half2(h[2], h[3]);
    reinterpret_cast<__half2*>(olo + base)[tid*2+0] = __halves2half2(l[0], l[1]);
    reinterpret_cast<__half2*>(olo + base)[tid*2+1] = __halves2half2(l[2], l[3]);
    #pragma unroll
    for (int j = 0; j < 4; j++) split_val(o1[j], h[j], l[j]);
    reinterpret_cast<__half2*>(ohi + base)[(tid+256)*2+0] = __halves2half2(h[0], h[1]);
    reinterpret_cast<__half2*>(ohi + base)[(tid+256)*2+1] = __halves2half2(h[2], h[3]);
    reinterpret_cast<__half2*>(olo + base)[(tid+256)*2+0] = __halves2half2(l[0], l[1]);
    reinterpret_cast<__half2*>(olo + base)[(tid+256)*2+1] = __halves2half2(l[2], l[3]);
}

// ---------------- Flash attention (causal, fp32, packed QKV) ----------------
// All hot-loop shared loads are LDS.128: Q/P rows load as broadcast float4.
#define QSTRIDE 132
#define KSTRIDE 68
#define PSTRIDE 68

__global__ __launch_bounds__(256) void flash_kernel(
    const float* __restrict__ QKV,
    __half* __restrict__ Ohi, __half* __restrict__ Olo)
{
    extern __shared__ float sm[];
    float* Qs = sm;
    float* Kt = Qs + 64*QSTRIDE;
    float* Vs = Kt + 128*KSTRIDE;
    float* Ps = Vs + 64*QSTRIDE;

    const int tid = threadIdx.x;
    const int tx = tid & 15;
    const int ty = tid >> 4;
    const int bh = blockIdx.y;
    const int b  = bh >> 4;
    const int h  = bh & 15;
    const int qb = blockIdx.x;
    const size_t rowbase = (size_t)b * SEQ;
    const int colbase = h * HDIM;
    const float scale = 0.088388347648318447f;

    #pragma unroll
    for (int it = 0; it < 8; ++it) {
        int idx = it * 256 + tid;
        int r  = idx >> 5;
        int c4 = (idx & 31) << 2;
        float4 qv = *reinterpret_cast<const float4*>(
            &QKV[(rowbase + qb*64 + r) * QKVLD + colbase + c4]);
        *reinterpret_cast<float4*>(&Qs[r*QSTRIDE + c4]) = qv;
    }

    float m[4], l[4], o[4][8];
    #pragma unroll
    for (int i = 0; i < 4; i++) {
        m[i] = -1e30f; l[i] = 0.0f;
        #pragma unroll
        for (int c = 0; c < 8; c++) o[i][c] = 0.0f;
    }

    for (int kb = 0; kb <= qb; ++kb) {
        __syncthreads();
        #pragma unroll
        for (int it = 0; it < 8; ++it) {
            int idx = it * 256 + tid;
            int r  = idx >> 5;
            int c4 = (idx & 31) << 2;
            const size_t grow = (rowbase + kb*64 + r) * (size_t)QKVLD + colbase + c4;
            float4 kv = *reinterpret_cast<const float4*>(&QKV[grow + HID]);
            Kt[(c4+0)*KSTRIDE + r] = kv.x;
            Kt[(c4+1)*KSTRIDE + r] = kv.y;
            Kt[(c4+2)*KSTRIDE + r] = kv.z;
            Kt[(c4+3)*KSTRIDE + r] = kv.w;
            float4 vv = *reinterpret_cast<const float4*>(&QKV[grow + 2*HID]);
            *reinterpret_cast<float4*>(&Vs[r*QSTRIDE + c4]) = vv;
        }
        __syncthreads();

        float s[4][4];
        #pragma unroll
        for (int i = 0; i < 4; i++)
            #pragma unroll
            for (int jj = 0; jj < 4; jj++) s[i][jj] = 0.0f;

        // QK: d unrolled by 4; K cols as float4(tx*4), Q rows as broadcast float4
        #pragma unroll 2
        for (int d4 = 0; d4 < HDIM/4; ++d4) {
            float4 kr[4];
            #pragma unroll
            for (int dd = 0; dd < 4; dd++)
                kr[dd] = *reinterpret_cast<const float4*>(&Kt[(d4*4 + dd)*KSTRIDE + tx*4]);
            #pragma unroll
            for (int i = 0; i < 4; i++) {
                const float4 q4 = *reinterpret_cast<const float4*>(&Qs[(ty*4 + i)*QSTRIDE + d4*4]);
                s[i][0] = fmaf(q4.x, kr[0].x, s[i][0]);
                s[i][1] = fmaf(q4.x, kr[0].y, s[i][1]);
                s[i][2] = fmaf(q4.x, kr[0].z, s[i][2]);
                s[i][3] = fmaf(q4.x, kr[0].w, s[i][3]);
                s[i][0] = fmaf(q4.y, kr[1].x, s[i][0]);
                s[i][1] = fmaf(q4.y, kr[1].y, s[i][1]);
                s[i][2] = fmaf(q4.y, kr[1].z, s[i][2]);
                s[i][3] = fmaf(q4.y, kr[1].w, s[i][3]);
                s[i][0] = fmaf(q4.z, kr[2].x, s[i][0]);
                s[i][1] = fmaf(q4.z, kr[2].y, s[i][1]);
                s[i][2] = fmaf(q4.z, kr[2].z, s[i][2]);
                s[i][3] = fmaf(q4.z, kr[2].w, s[i][3]);
                s[i][0] = fmaf(q4.w, kr[3].x, s[i][0]);
                s[i][1] = fmaf(q4.w, kr[3].y, s[i][1]);
                s[i][2] = fmaf(q4.w, kr[3].z, s[i][2]);
                s[i][3] = fmaf(q4.w, kr[3].w, s[i][3]);
            }
        }

        const bool diag = (kb == qb);
        #pragma unroll
        for (int i = 0; i < 4; i++) {
            const int qg = qb*64 + ty*4 + i;
            float mx = -1e30f;
            #pragma unroll
            for (int jj = 0; jj < 4; jj++) {
                float v = s[i][jj] * scale;
                if (diag && (kb*64 + tx*4 + jj) > qg) v = -1e30f;
                s[i][jj] = v;
                mx = fmaxf(mx, v);
            }
            #pragma unroll
            for (int off = 8; off > 0; off >>= 1)
                mx = fmaxf(mx, __shfl_xor_sync(0xffffffffu, mx, off));
            float mnew = fmaxf(m[i], mx);
            float corr = __expf(m[i] - mnew);
            float rs = 0.0f;
            #pragma unroll
            for (int jj = 0; jj < 4; jj++) {
                float p = __expf(s[i][jj] - mnew);
                s[i][jj] = p;
                rs += p;
            }
            #pragma unroll
            for (int off = 8; off > 0; off >>= 1)
                rs += __shfl_xor_sync(0xffffffffu, rs, off);
            l[i] = l[i]*corr + rs;
            m[i] = mnew;
            #pragma unroll
            for (int c = 0; c < 8; c++) o[i][c] *= corr;
            float4 pv; pv.x = s[i][0]; pv.y = s[i][1]; pv.z = s[i][2]; pv.w = s[i][3];
            *reinterpret_cast<float4*>(&Ps[(ty*4 + i)*PSTRIDE + tx*4]) = pv;
        }
        __syncthreads();

        // PV: j unrolled by 4; P rows as broadcast float4, V as float4(tx*4)
        #pragma unroll 2
        for (int j4 = 0; j4 < 16; ++j4) {
            float4 p4[4];
            #pragma unroll
            for (int i = 0; i < 4; i++)
                p4[i] = *reinterpret_cast<const float4*>(&Ps[(ty*4 + i)*PSTRIDE + j4*4]);
            #pragma unroll
            for (int jj = 0; jj < 4; jj++) {
                const int j = j4*4 + jj;
                const float4 va = *reinterpret_cast<const float4*>(&Vs[j*QSTRIDE + tx*4]);
                const float4 vb = *reinterpret_cast<const float4*>(&Vs[j*QSTRIDE + 64 + tx*4]);
                #pragma unroll
                for (int i = 0; i < 4; i++) {
                    const float p = (jj == 0) ? p4[i].x : (jj == 1) ? p4[i].y
                                  : (jj == 2) ? p4[i].z : p4[i].w;
                    o[i][0] = fmaf(p, va.x, o[i][0]);
                    o[i][1] = fmaf(p, va.y, o[i][1]);
                    o[i][2] = fmaf(p, va.z, o[i][2]);
                    o[i][3] = fmaf(p, va.w, o[i][3]);
                    o[i][4] = fmaf(p, vb.x, o[i][4]);
                    o[i][5] = fmaf(p, vb.y, o[i][5]);
                    o[i][6] = fmaf(p, vb.z, o[i][6]);
                    o[i][7] = fmaf(p, vb.w, o[i][7]);
                }
            }
        }
    }

    #pragma unroll
    for (int i = 0; i < 4; i++) {
        const float inv = 1.0f / l[i];
        const size_t r = rowbase + qb*64 + ty*4 + i;
        __half hh[8], ll[8];
        #pragma unroll
        for (int c = 0; c < 8; c++) split_val(o[i][c] * inv, hh[c], ll[c]);
        __half2* oh0 = reinterpret_cast<__half2*>(&Ohi[r*HID + colbase + tx*4]);
        __half2* ol0 = reinterpret_cast<__half2*>(&Olo[r*HID + colbase + tx*4]);
        oh0[0] = __halves2half2(hh[0], hh[1]);  oh0[1] = __halves2half2(hh[2], hh[3]);
        ol0[0] = __halves2half2(ll[0], ll[1]);  ol0[1] = __halves2half2(ll[2], ll[3]);
        __half2* oh1 = reinterpret_cast<__half2*>(&Ohi[r*HID + colbase + 64 + tx*4]);
        __half2* ol1 = reinterpret_cast<__half2*>(&Olo[r*HID + colbase + 64 + tx*4]);
        oh1[0] = __halves2half2(hh[4], hh[5]);  oh1[1] = __halves2half2(hh[6], hh[7]);
        ol1[0] = __halves2half2(ll[4], ll[5]);  ol1[1] = __halves2half2(ll[6], ll[7]);
    }
}

// ============================ host side =====================================
extern "C" void kernel_launch(void* const* d_in, const int* in_sizes, int n_in,
                              void* d_out, int out_size)
{
    const float* x     = (const float*)d_in[0];
    const float* wq    = (const float*)d_in[2];
    const float* wk    = (const float*)d_in[3];
    const float* wv    = (const float*)d_in[4];
    const float* wo    = (const float*)d_in[5];
    const float* w_in  = (const float*)d_in[6];
    const float* w_out = (const float*)d_in[7];
    const float* ln1_g = (const float*)d_in[8];
    const float* ln1_b = (const float*)d_in[9];
    const float* ln2_g = (const float*)d_in[10];
    const float* ln2_b = (const float*)d_in[11];
    float* out = (float*)d_out;

    float *qkv, *h;
    __half *xnh,*xnl,*atth,*attl,*hnh,*hnl,*ffh,*ffl;
    __half *wqkvh,*wqkvl,*woh,*wol,*winh,*winl,*wouth,*woutl;
    cudaGetSymbolAddress((void**)&qkv, g_qkv);
    cudaGetSymbolAddress((void**)&h,  g_h);
    cudaGetSymbolAddress((void**)&xnh, g_xnh);   cudaGetSymbolAddress((void**)&xnl, g_xnl);
    cudaGetSymbolAddress((void**)&atth, g_atth); cudaGetSymbolAddress((void**)&attl, g_attl);
    cudaGetSymbolAddress((void**)&hnh, g_hnh);   cudaGetSymbolAddress((void**)&hnl, g_hnl);
    cudaGetSymbolAddress((void**)&ffh, g_ffh);   cudaGetSymbolAddress((void**)&ffl, g_ffl);
    cudaGetSymbolAddress((void**)&wqkvh, g_wqkvh); cudaGetSymbolAddress((void**)&wqkvl, g_wqkvl);
    cudaGetSymbolAddress((void**)&woh, g_woh);   cudaGetSymbolAddress((void**)&wol, g_wol);
    cudaGetSymbolAddress((void**)&winh, g_winh); cudaGetSymbolAddress((void**)&winl, g_winl);
    cudaGetSymbolAddress((void**)&wouth, g_wouth); cudaGetSymbolAddress((void**)&woutl, g_woutl);

    cudaFuncSetAttribute(tc_gemm<0>, cudaFuncAttributeMaxDynamicSharedMemorySize, GEMM_SMEM);
    cudaFuncSetAttribute(tc_gemm<1>, cudaFuncAttributeMaxDynamicSharedMemorySize, GEMM_SMEM);
    cudaFuncSetAttribute(tc_gemm<2>, cudaFuncAttributeMaxDynamicSharedMemorySize, GEMM_SMEM);
    const int smem_flash = (64*QSTRIDE + 128*KSTRIDE + 64*QSTRIDE + 64*PSTRIDE) * 4;
    cudaFuncSetAttribute(flash_kernel, cudaFuncAttributeMaxDynamicSharedMemorySize, smem_flash);

    // 0. split weights
    {
        const int t = 256;
        dim3 gq((HID*HID/4 + t-1)/t, 4);
        splitqkv_kernel<<<gq, t>>>(wq, wk, wv, wo, wqkvh, wqkvl, woh, wol, HID*HID/4);
        dim3 g2((HID*FFD/4 + t-1)/t, 2);
        split2_kernel<<<g2, t>>>(w_in, winh, winl, w_out, wouth, woutl, HID*FFD/4);
    }

    // 1. LN1 -> split
    ln_kernel<<<ROWS, 256>>>(x, ln1_g, ln1_b, xnh, xnl);

    // 2. fused QKV projection
    dim3 gqkv(QKVLD/BN, ROWS/BM);
    tc_gemm<0><<<gqkv, 256, GEMM_SMEM>>>(xnh, xnl, wqkvh, wqkvl, nullptr, qkv,
                                         nullptr, nullptr, QKVLD, HID);

    // 3. causal flash attention
    dim3 gattn(SEQ/64, BATCH*NHEAD);
    flash_kernel<<<gattn, 256, smem_flash>>>(qkv, atth, attl);

    // 4. output projection + residual -> h
    dim3 gproj(HID/BN, ROWS/BM);
    tc_gemm<1><<<gproj, 256, GEMM_SMEM>>>(atth, attl, woh, wol, x, h,
                                          nullptr, nullptr, HID, HID);

    // 5. LN2 -> split
    ln_kernel<<<ROWS, 256>>>(h, ln2_g, ln2_b, hnh, hnl);

    // 6. FFN up + GELU
    dim3 gff1(FFD/BN, ROWS/BM);
    tc_gemm<2><<<gff1, 256, GEMM_SMEM>>>(hnh, hnl, winh, winl, nullptr, nullptr,
                                         ffh, ffl, FFD, HID);

    // 7. FFN down + residual -> d_out
    dim3 gff2(HID/BN, ROWS/BM);
    tc_gemm<1><<<gff2, 256, GEMM_SMEM>>>(ffh, ffl, wouth, woutl, h, out,
                                         nullptr, nullptr, HID, FFD);
}

// round 9
// speedup vs baseline: 1.4813x; 1.2758x over previous
#include <cuda_runtime.h>
#include <cuda_fp16.h>
#include <math.h>
#include <cstdint>

#define BATCH 2
#define SEQ   2048
#define HID   2048
#define NHEAD 16
#define HDIM  128
#define FFD   8192
#define ROWS  (BATCH*SEQ)   // 4096
#define QKVLD (3*HID)       // 6144

// ---------------- scratch ---------------------------------------------------
__device__ float g_qkv[(size_t)ROWS*QKVLD];   // packed q|k|v
__device__ float g_h [ROWS*HID];
__device__ __half g_xnh[ROWS*HID];
__device__ __half g_xnl[ROWS*HID];
__device__ __half g_atth[ROWS*HID];
__device__ __half g_attl[ROWS*HID];
__device__ __half g_hnh[ROWS*HID];
__device__ __half g_hnl[ROWS*HID];
__device__ __half g_ffh[(size_t)ROWS*FFD];
__device__ __half g_ffl[(size_t)ROWS*FFD];
// weights: plain RN-fp16 (2-term split scheme; weight lo-term dropped)
__device__ __half g_wqkv16[(size_t)HID*QKVLD];  // packed [K=HID][6144]
__device__ __half g_wo16[HID*HID];
__device__ __half g_win16[(size_t)HID*FFD];
__device__ __half g_wout16[(size_t)HID*FFD];

// ============================ helpers ========================================
__device__ __forceinline__ uint32_t smem_u32(const void* p) {
    uint32_t a;
    asm("{ .reg .u64 t; cvta.to.shared.u64 t, %1; cvt.u32.u64 %0, t; }"
        : "=r"(a) : "l"(p));
    return a;
}
__device__ __forceinline__ void cp16(uint32_t dst, const void* src) {
    asm volatile("cp.async.cg.shared.global [%0], [%1], 16;" :: "r"(dst), "l"(src));
}
__device__ __forceinline__ void cp_commit() { asm volatile("cp.async.commit_group;"); }
template<int N> __device__ __forceinline__ void cp_wait() {
    asm volatile("cp.async.wait_group %0;" :: "n"(N));
}
__device__ __forceinline__ void ldsm_x4(uint32_t* r, uint32_t addr) {
    asm volatile("ldmatrix.sync.aligned.m8n8.x4.shared.b16 {%0,%1,%2,%3}, [%4];"
        : "=r"(r[0]), "=r"(r[1]), "=r"(r[2]), "=r"(r[3]) : "r"(addr));
}
__device__ __forceinline__ void ldsm_x4_t(uint32_t* r, uint32_t addr) {
    asm volatile("ldmatrix.sync.aligned.m8n8.x4.trans.shared.b16 {%0,%1,%2,%3}, [%4];"
        : "=r"(r[0]), "=r"(r[1]), "=r"(r[2]), "=r"(r[3]) : "r"(addr));
}
__device__ __forceinline__ void mma_f16(float* c, const uint32_t* a, const uint32_t* b) {
    asm volatile("mma.sync.aligned.m16n8k16.row.col.f32.f16.f16.f32 "
        "{%0,%1,%2,%3}, {%4,%5,%6,%7}, {%8,%9}, {%0,%1,%2,%3};"
        : "+f"(c[0]), "+f"(c[1]), "+f"(c[2]), "+f"(c[3])
        : "r"(a[0]), "r"(a[1]), "r"(a[2]), "r"(a[3]), "r"(b[0]), "r"(b[1]));
}
__device__ __forceinline__ float gelu_tanh(float x) {
    float x3 = x * x * x;
    float t  = tanhf(0.7978845608028654f * (x + 0.044715f * x3));
    return 0.5f * x * (1.0f + t);
}
__device__ __forceinline__ void split_val(float v, __half& hi, __half& lo) {
    hi = __float2half_rn(v);
    lo = __float2half_rn(v - __half2float(hi));
}

// ============================================================================
// 2-term split-fp16 GEMM: C = (Ahi + Alo) * B16
// A split in fp16 hi/lo (full compensation); B plain RN-fp16 (unbiased error).
// 2 CTAs/SM, 1 barrier per k-tile, early cp.async refill.
// ============================================================================
#define BM 128
#define BN 128
#define BKH 32
#define LDAH 40
#define LDBH 136
#define ASZH (BM*LDAH)      // 5120 halves
#define BSZH (BKH*LDBH)     // 4352 halves
#define STG 3
#define STAGEH (2*ASZH + BSZH)      // 14592 halves
#define GEMM_SMEM (STG*STAGEH*2)    // 87552 bytes -> 2 CTAs/SM easily

template<int ACT>
__global__ __launch_bounds__(256, 2) void tc_gemm(
    const __half* __restrict__ Ahi, const __half* __restrict__ Alo,
    const __half* __restrict__ B16,
    const float* __restrict__ Res, float* __restrict__ Cf,
    __half* __restrict__ Chi, __half* __restrict__ Clo,
    int N_, int K)
{
    extern __shared__ __align__(16) __half smem[];

    const int tid  = threadIdx.x;
    const int wid  = tid >> 5;
    const int lane = tid & 31;
    const int gid  = lane >> 2;
    const int tg   = lane & 3;
    const int wm   = wid & 3;
    const int wn   = wid >> 2;
    const int bm = blockIdx.y * BM;
    const int bn = blockIdx.x * BN;
    const int nK = K / BKH;

    const int a_m = lane & 15;
    const int a_k = (lane >> 4) * 8;
    const int b_k = ((lane >> 3) & 1) * 8 + (lane & 7);
    const int b_n = (lane >> 4) * 8;

    auto load_stage = [&](int s, int kt) {
        const int k0 = kt * BKH;
        __half* Ah = smem + s*STAGEH;
        __half* Al = Ah + ASZH;
        __half* Bs = Al + ASZH;
        #pragma unroll
        for (int i = 0; i < 2; i++) {
            const int c  = tid + 256*i;
            const int ar = c >> 2, ak = (c & 3) << 3;
            cp16(smem_u32(&Ah[ar*LDAH + ak]), &Ahi[(size_t)(bm + ar)*K + k0 + ak]);
            cp16(smem_u32(&Al[ar*LDAH + ak]), &Alo[(size_t)(bm + ar)*K + k0 + ak]);
            const int bk = c >> 4, bnn = (c & 15) << 3;
            cp16(smem_u32(&Bs[bk*LDBH + bnn]), &B16[(size_t)(k0 + bk)*N_ + bn + bnn]);
        }
        cp_commit();
    };

    float acc[2][8][4];
    #pragma unroll
    for (int mt = 0; mt < 2; mt++)
        #pragma unroll
        for (int nt = 0; nt < 8; nt++)
            #pragma unroll
            for (int r = 0; r < 4; r++) acc[mt][nt][r] = 0.0f;

    load_stage(0, 0);
    load_stage(1, 1);

    for (int kt = 0; kt < nK; kt++) {
        cp_wait<1>();
        __syncthreads();
        // refill targets stage whose readers finished at kt-1 (reg deps + barrier)
        if (kt + STG - 1 < nK)
            load_stage((kt + STG - 1) % STG, kt + STG - 1);

        const int s = kt % STG;
        const __half* Ah = smem + s*STAGEH;
        const __half* Al = Ah + ASZH;
        const __half* Bs = Al + ASZH;

        #pragma unroll
        for (int kk = 0; kk < 2; kk++) {
            uint32_t ah[2][4], al[2][4];
            #pragma unroll
            for (int mt = 0; mt < 2; mt++) {
                const int mrow = wm*32 + mt*16 + a_m;
                const int koff = kk*16 + a_k;
                ldsm_x4(ah[mt], smem_u32(&Ah[mrow*LDAH + koff]));
                ldsm_x4(al[mt], smem_u32(&Al[mrow*LDAH + koff]));
            }
            uint32_t bh[4][4];
            #pragma unroll
            for (int ng = 0; ng < 4; ng++) {
                const int koff = kk*16 + b_k;
                const int noff = wn*64 + ng*16 + b_n;
                ldsm_x4_t(bh[ng], smem_u32(&Bs[koff*LDBH + noff]));
            }
            #pragma unroll
            for (int mt = 0; mt < 2; mt++)
                #pragma unroll
                for (int nt = 0; nt < 8; nt++) {
                    const uint32_t* bhp = &bh[nt >> 1][(nt & 1) * 2];
                    mma_f16(acc[mt][nt], ah[mt], bhp);
                    mma_f16(acc[mt][nt], al[mt], bhp);
                }
        }
    }

    #pragma unroll
    for (int mt = 0; mt < 2; mt++) {
        #pragma unroll
        for (int half_ = 0; half_ < 2; half_++) {
            const int r = bm + wm*32 + mt*16 + gid + half_*8;
            #pragma unroll
            for (int nt = 0; nt < 8; nt++) {
                const int cc = bn + wn*64 + nt*8 + tg*2;
                float v0 = acc[mt][nt][half_*2 + 0];
                float v1 = acc[mt][nt][half_*2 + 1];
                if (ACT == 2) {
                    v0 = gelu_tanh(v0); v1 = gelu_tanh(v1);
                    __half h0, l0, h1, l1;
                    split_val(v0, h0, l0); split_val(v1, h1, l1);
                    *reinterpret_cast<__half2*>(&Chi[(size_t)r*N_ + cc]) = __halves2half2(h0, h1);
                    *reinterpret_cast<__half2*>(&Clo[(size_t)r*N_ + cc]) = __halves2half2(l0, l1);
                } else {
                    if (ACT == 1) {
                        const float2 rr = *reinterpret_cast<const float2*>(&Res[(size_t)r*N_ + cc]);
                        v0 += rr.x; v1 += rr.y;
                    }
                    float2 o; o.x = v0; o.y = v1;
                    *reinterpret_cast<float2*>(&Cf[(size_t)r*N_ + cc]) = o;
                }
            }
        }
    }
}

// ------------- weight conversion: fp32 -> RN fp16 ---------------------------
// wq/wk/wv -> packed [HID][6144] at column offsets 0/2048/4096; wo separate.
__global__ void convqkv_kernel(const float* __restrict__ wq,
                               const float* __restrict__ wk,
                               const float* __restrict__ wv,
                               const float* __restrict__ wo,
                               __half* __restrict__ qkv16,
                               __half* __restrict__ wo16,
                               int n4)
{
    const int i = blockIdx.x*blockDim.x + threadIdx.x;
    if (i >= n4) return;
    const int y = blockIdx.y;
    const float* in = (y == 0) ? wq : (y == 1) ? wk : (y == 2) ? wv : wo;
    const int e   = i * 4;
    const int row = e >> 11;
    const int col = e & 2047;
    float4 v = reinterpret_cast<const float4*>(in)[i];
    __half2 p0 = __halves2half2(__float2half_rn(v.x), __float2half_rn(v.y));
    __half2 p1 = __halves2half2(__float2half_rn(v.z), __float2half_rn(v.w));
    __half* dst; size_t o;
    if (y < 3) { dst = qkv16; o = (size_t)row*QKVLD + y*HID + col; }
    else       { dst = wo16;  o = (size_t)row*HID + col; }
    reinterpret_cast<__half2*>(dst + o)[0] = p0;
    reinterpret_cast<__half2*>(dst + o)[1] = p1;
}
__global__ void conv2_kernel(const float* __restrict__ w0, __half* o0,
                             const float* __restrict__ w1, __half* o1,
                             int n4)
{
    const float* in = blockIdx.y ? w1 : w0;
    __half* dst = blockIdx.y ? o1 : o0;
    const int i = blockIdx.x*blockDim.x + threadIdx.x;
    if (i >= n4) return;
    float4 v = reinterpret_cast<const float4*>(in)[i];
    reinterpret_cast<__half2*>(dst)[2*i+0] =
        __halves2half2(__float2half_rn(v.x), __float2half_rn(v.y));
    reinterpret_cast<__half2*>(dst)[2*i+1] =
        __halves2half2(__float2half_rn(v.z), __float2half_rn(v.w));
}

// ---------------- LayerNorm -> split fp16 outputs ---------------------------
__global__ void ln_kernel(const float* __restrict__ x,
                          const float* __restrict__ g,
                          const float* __restrict__ b,
                          __half* __restrict__ ohi, __half* __restrict__ olo)
{
    const int row = blockIdx.x;
    const int tid = threadIdx.x;
    const float* xr = x + (size_t)row * HID;

    float4 v0 = reinterpret_cast<const float4*>(xr)[tid];
    float4 v1 = reinterpret_cast<const float4*>(xr)[tid + 256];

    __shared__ float red[8];

    float s = v0.x+v0.y+v0.z+v0.w + v1.x+v1.y+v1.z+v1.w;
    #pragma unroll
    for (int o = 16; o > 0; o >>= 1) s += __shfl_xor_sync(0xffffffffu, s, o);
    if ((tid & 31) == 0) red[tid >> 5] = s;
    __syncthreads();
    float mu = (red[0]+red[1]+red[2]+red[3]+red[4]+red[5]+red[6]+red[7]) * (1.0f/HID);
    __syncthreads();

    float d0x=v0.x-mu, d0y=v0.y-mu, d0z=v0.z-mu, d0w=v0.w-mu;
    float d1x=v1.x-mu, d1y=v1.y-mu, d1z=v1.z-mu, d1w=v1.w-mu;
    float sq = d0x*d0x+d0y*d0y+d0z*d0z+d0w*d0w + d1x*d1x+d1y*d1y+d1z*d1z+d1w*d1w;
    #pragma unroll
    for (int o = 16; o > 0; o >>= 1) sq += __shfl_xor_sync(0xffffffffu, sq, o);
    if ((tid & 31) == 0) red[tid >> 5] = sq;
    __syncthreads();
    float var = (red[0]+red[1]+red[2]+red[3]+red[4]+red[5]+red[6]+red[7]) * (1.0f/HID);
    float rstd = rsqrtf(var + 1e-5f);

    float4 g0 = reinterpret_cast<const float4*>(g)[tid];
    float4 g1 = reinterpret_cast<const float4*>(g)[tid + 256];
    float4 b0 = reinterpret_cast<const float4*>(b)[tid];
    float4 b1 = reinterpret_cast<const float4*>(b)[tid + 256];

    float o0[4] = { d0x*rstd*g0.x + b0.x, d0y*rstd*g0.y + b0.y,
                    d0z*rstd*g0.z + b0.z, d0w*rstd*g0.w + b0.w };
    float o1[4] = { d1x*rstd*g1.x + b1.x, d1y*rstd*g1.y + b1.y,
                    d1z*rstd*g1.z + b1.z, d1w*rstd*g1.w + b1.w };

    const size_t base = (size_t)row * HID;
    __half h[4], l[4];
    #pragma unroll
    for (int j = 0; j < 4; j++) split_val(o0[j], h[j], l[j]);
    reinterpret_cast<__half2*>(ohi + base)[tid*2+0] = __halves2half2(h[0], h[1]);
    reinterpret_cast<__half2*>(ohi + base)[tid*2+1] = __halves2half2(h[2], h[3]);
    reinterpret_cast<__half2*>(olo + base)[tid*2+0] = __halves2half2(l[0], l[1]);
    reinterpret_cast<__half2*>(olo + base)[tid*2+1] = __halves2half2(l[2], l[3]);
    #pragma unroll
    for (int j = 0; j < 4; j++) split_val(o1[j], h[j], l[j]);
    reinterpret_cast<__half2*>(ohi + base)[(tid+256)*2+0] = __halves2half2(h[0], h[1]);
    reinterpret_cast<__half2*>(ohi + base)[(tid+256)*2+1] = __halves2half2(h[2], h[3]);
    reinterpret_cast<__half2*>(olo + base)[(tid+256)*2+0] = __halves2half2(l[0], l[1]);
    reinterpret_cast<__half2*>(olo + base)[(tid+256)*2+1] = __halves2half2(l[2], l[3]);
}

// ---------------- Flash attention (causal, fp32, packed QKV) ----------------
#define QSTRIDE 132
#define KSTRIDE 68
#define PSTRIDE 68

__global__ __launch_bounds__(256) void flash_kernel(
    const float* __restrict__ QKV,
    __half* __restrict__ Ohi, __half* __restrict__ Olo)
{
    extern __shared__ float sm[];
    float* Qs = sm;
    float* Kt = Qs + 64*QSTRIDE;
    float* Vs = Kt + 128*KSTRIDE;
    float* Ps = Vs + 64*QSTRIDE;

    const int tid = threadIdx.x;
    const int tx = tid & 15;
    const int ty = tid >> 4;
    const int bh = blockIdx.y;
    const int b  = bh >> 4;
    const int h  = bh & 15;
    const int qb = blockIdx.x;
    const size_t rowbase = (size_t)b * SEQ;
    const int colbase = h * HDIM;
    const float scale = 0.088388347648318447f;

    #pragma unroll
    for (int it = 0; it < 8; ++it) {
        int idx = it * 256 + tid;
        int r  = idx >> 5;
        int c4 = (idx & 31) << 2;
        float4 qv = *reinterpret_cast<const float4*>(
            &QKV[(rowbase + qb*64 + r) * QKVLD + colbase + c4]);
        *reinterpret_cast<float4*>(&Qs[r*QSTRIDE + c4]) = qv;
    }

    float m[4], l[4], o[4][8];
    #pragma unroll
    for (int i = 0; i < 4; i++) {
        m[i] = -1e30f; l[i] = 0.0f;
        #pragma unroll
        for (int c = 0; c < 8; c++) o[i][c] = 0.0f;
    }

    for (int kb = 0; kb <= qb; ++kb) {
        __syncthreads();
        #pragma unroll
        for (int it = 0; it < 8; ++it) {
            int idx = it * 256 + tid;
            int r  = idx >> 5;
            int c4 = (idx & 31) << 2;
            const size_t grow = (rowbase + kb*64 + r) * (size_t)QKVLD + colbase + c4;
            float4 kv = *reinterpret_cast<const float4*>(&QKV[grow + HID]);
            Kt[(c4+0)*KSTRIDE + r] = kv.x;
            Kt[(c4+1)*KSTRIDE + r] = kv.y;
            Kt[(c4+2)*KSTRIDE + r] = kv.z;
            Kt[(c4+3)*KSTRIDE + r] = kv.w;
            float4 vv = *reinterpret_cast<const float4*>(&QKV[grow + 2*HID]);
            *reinterpret_cast<float4*>(&Vs[r*QSTRIDE + c4]) = vv;
        }
        __syncthreads();

        float s[4][4];
        #pragma unroll
        for (int i = 0; i < 4; i++)
            #pragma unroll
            for (int jj = 0; jj < 4; jj++) s[i][jj] = 0.0f;

        #pragma unroll 2
        for (int d4 = 0; d4 < HDIM/4; ++d4) {
            float4 kr[4];
            #pragma unroll
            for (int dd = 0; dd < 4; dd++)
                kr[dd] = *reinterpret_cast<const float4*>(&Kt[(d4*4 + dd)*KSTRIDE + tx*4]);
            #pragma unroll
            for (int i = 0; i < 4; i++) {
                const float4 q4 = *reinterpret_cast<const float4*>(&Qs[(ty*4 + i)*QSTRIDE + d4*4]);
                s[i][0] = fmaf(q4.x, kr[0].x, s[i][0]);
                s[i][1] = fmaf(q4.x, kr[0].y, s[i][1]);
                s[i][2] = fmaf(q4.x, kr[0].z, s[i][2]);
                s[i][3] = fmaf(q4.x, kr[0].w, s[i][3]);
                s[i][0] = fmaf(q4.y, kr[1].x, s[i][0]);
                s[i][1] = fmaf(q4.y, kr[1].y, s[i][1]);
                s[i][2] = fmaf(q4.y, kr[1].z, s[i][2]);
                s[i][3] = fmaf(q4.y, kr[1].w, s[i][3]);
                s[i][0] = fmaf(q4.z, kr[2].x, s[i][0]);
                s[i][1] = fmaf(q4.z, kr[2].y, s[i][1]);
                s[i][2] = fmaf(q4.z, kr[2].z, s[i][2]);
                s[i][3] = fmaf(q4.z, kr[2].w, s[i][3]);
                s[i][0] = fmaf(q4.w, kr[3].x, s[i][0]);
                s[i][1] = fmaf(q4.w, kr[3].y, s[i][1]);
                s[i][2] = fmaf(q4.w, kr[3].z, s[i][2]);
                s[i][3] = fmaf(q4.w, kr[3].w, s[i][3]);
            }
        }

        const bool diag = (kb == qb);
        #pragma unroll
        for (int i = 0; i < 4; i++) {
            const int qg = qb*64 + ty*4 + i;
            float mx = -1e30f;
            #pragma unroll
            for (int jj = 0; jj < 4; jj++) {
                float v = s[i][jj] * scale;
                if (diag && (kb*64 + tx*4 + jj) > qg) v = -1e30f;
                s[i][jj] = v;
                mx = fmaxf(mx, v);
            }
            #pragma unroll
            for (int off = 8; off > 0; off >>= 1)
                mx = fmaxf(mx, __shfl_xor_sync(0xffffffffu, mx, off));
            float mnew = fmaxf(m[i], mx);
            float corr = __expf(m[i] - mnew);
            float rs = 0.0f;
            #pragma unroll
            for (int jj = 0; jj < 4; jj++) {
                float p = __expf(s[i][jj] - mnew);
                s[i][jj] = p;
                rs += p;
            }
            #pragma unroll
            for (int off = 8; off > 0; off >>= 1)
                rs += __shfl_xor_sync(0xffffffffu, rs, off);
            l[i] = l[i]*corr + rs;
            m[i] = mnew;
            #pragma unroll
            for (int c = 0; c < 8; c++) o[i][c] *= corr;
            float4 pv; pv.x = s[i][0]; pv.y = s[i][1]; pv.z = s[i][2]; pv.w = s[i][3];
            *reinterpret_cast<float4*>(&Ps[(ty*4 + i)*PSTRIDE + tx*4]) = pv;
        }
        __syncthreads();

        #pragma unroll 2
        for (int j4 = 0; j4 < 16; ++j4) {
            float4 p4[4];
            #pragma unroll
            for (int i = 0; i < 4; i++)
                p4[i] = *reinterpret_cast<const float4*>(&Ps[(ty*4 + i)*PSTRIDE + j4*4]);
            #pragma unroll
            for (int jj = 0; jj < 4; jj++) {
                const int j = j4*4 + jj;
                const float4 va = *reinterpret_cast<const float4*>(&Vs[j*QSTRIDE + tx*4]);
                const float4 vb = *reinterpret_cast<const float4*>(&Vs[j*QSTRIDE + 64 + tx*4]);
                #pragma unroll
                for (int i = 0; i < 4; i++) {
                    const float p = (jj == 0) ? p4[i].x : (jj == 1) ? p4[i].y
                                  : (jj == 2) ? p4[i].z : p4[i].w;
                    o[i][0] = fmaf(p, va.x, o[i][0]);
                    o[i][1] = fmaf(p, va.y, o[i][1]);
                    o[i][2] = fmaf(p, va.z, o[i][2]);
                    o[i][3] = fmaf(p, va.w, o[i][3]);
                    o[i][4] = fmaf(p, vb.x, o[i][4]);
                    o[i][5] = fmaf(p, vb.y, o[i][5]);
                    o[i][6] = fmaf(p, vb.z, o[i][6]);
                    o[i][7] = fmaf(p, vb.w, o[i][7]);
                }
            }
        }
    }

    #pragma unroll
    for (int i = 0; i < 4; i++) {
        const float inv = 1.0f / l[i];
        const size_t r = rowbase + qb*64 + ty*4 + i;
        __half hh[8], ll[8];
        #pragma unroll
        for (int c = 0; c < 8; c++) split_val(o[i][c] * inv, hh[c], ll[c]);
        __half2* oh0 = reinterpret_cast<__half2*>(&Ohi[r*HID + colbase + tx*4]);
        __half2* ol0 = reinterpret_cast<__half2*>(&Olo[r*HID + colbase + tx*4]);
        oh0[0] = __halves2half2(hh[0], hh[1]);  oh0[1] = __halves2half2(hh[2], hh[3]);
        ol0[0] = __halves2half2(ll[0], ll[1]);  ol0[1] = __halves2half2(ll[2], ll[3]);
        __half2* oh1 = reinterpret_cast<__half2*>(&Ohi[r*HID + colbase + 64 + tx*4]);
        __half2* ol1 = reinterpret_cast<__half2*>(&Olo[r*HID + colbase + 64 + tx*4]);
        oh1[0] = __halves2half2(hh[4], hh[5]);  oh1[1] = __halves2half2(hh[6], hh[7]);
        ol1[0] = __halves2half2(ll[4], ll[5]);  ol1[1] = __halves2half2(ll[6], ll[7]);
    }
}

// ============================ host side =====================================
extern "C" void kernel_launch(void* const* d_in, const int* in_sizes, int n_in,
                              void* d_out, int out_size)
{
    const float* x     = (const float*)d_in[0];
    const float* wq    = (const float*)d_in[2];
    const float* wk    = (const float*)d_in[3];
    const float* wv    = (const float*)d_in[4];
    const float* wo    = (const float*)d_in[5];
    const float* w_in  = (const float*)d_in[6];
    const float* w_out = (const float*)d_in[7];
    const float* ln1_g = (const float*)d_in[8];
    const float* ln1_b = (const float*)d_in[9];
    const float* ln2_g = (const float*)d_in[10];
    const float* ln2_b = (const float*)d_in[11];
    float* out = (float*)d_out;

    float *qkv, *h;
    __half *xnh,*xnl,*atth,*attl,*hnh,*hnl,*ffh,*ffl;
    __half *wqkv16,*wo16,*win16,*wout16;
    cudaGetSymbolAddress((void**)&qkv, g_qkv);
    cudaGetSymbolAddress((void**)&h,  g_h);
    cudaGetSymbolAddress((void**)&xnh, g_xnh);   cudaGetSymbolAddress((void**)&xnl, g_xnl);
    cudaGetSymbolAddress((void**)&atth, g_atth); cudaGetSymbolAddress((void**)&attl, g_attl);
    cudaGetSymbolAddress((void**)&hnh, g_hnh);   cudaGetSymbolAddress((void**)&hnl, g_hnl);
    cudaGetSymbolAddress((void**)&ffh, g_ffh);   cudaGetSymbolAddress((void**)&ffl, g_ffl);
    cudaGetSymbolAddress((void**)&wqkv16, g_wqkv16);
    cudaGetSymbolAddress((void**)&wo16, g_wo16);
    cudaGetSymbolAddress((void**)&win16, g_win16);
    cudaGetSymbolAddress((void**)&wout16, g_wout16);

    cudaFuncSetAttribute(tc_gemm<0>, cudaFuncAttributeMaxDynamicSharedMemorySize, GEMM_SMEM);
    cudaFuncSetAttribute(tc_gemm<1>, cudaFuncAttributeMaxDynamicSharedMemorySize, GEMM_SMEM);
    cudaFuncSetAttribute(tc_gemm<2>, cudaFuncAttributeMaxDynamicSharedMemorySize, GEMM_SMEM);
    const int smem_flash = (64*QSTRIDE + 128*KSTRIDE + 64*QSTRIDE + 64*PSTRIDE) * 4;
    cudaFuncSetAttribute(flash_kernel, cudaFuncAttributeMaxDynamicSharedMemorySize, smem_flash);

    // 0. convert weights to RN-fp16
    {
        const int t = 256;
        dim3 gq((HID*HID/4 + t-1)/t, 4);
        convqkv_kernel<<<gq, t>>>(wq, wk, wv, wo, wqkv16, wo16, HID*HID/4);
        dim3 g2((HID*FFD/4 + t-1)/t, 2);
        conv2_kernel<<<g2, t>>>(w_in, win16, w_out, wout16, HID*FFD/4);
    }

    // 1. LN1 -> split
    ln_kernel<<<ROWS, 256>>>(x, ln1_g, ln1_b, xnh, xnl);

    // 2. fused QKV projection
    dim3 gqkv(QKVLD/BN, ROWS/BM);
    tc_gemm<0><<<gqkv, 256, GEMM_SMEM>>>(xnh, xnl, wqkv16, nullptr, qkv,
                                         nullptr, nullptr, QKVLD, HID);

    // 3. causal flash attention
    dim3 gattn(SEQ/64, BATCH*NHEAD);
    flash_kernel<<<gattn, 256, smem_flash>>>(qkv, atth, attl);

    // 4. output projection + residual -> h
    dim3 gproj(HID/BN, ROWS/BM);
    tc_gemm<1><<<gproj, 256, GEMM_SMEM>>>(atth, attl, wo16, x, h,
                                          nullptr, nullptr, HID, HID);

    // 5. LN2 -> split
    ln_kernel<<<ROWS, 256>>>(h, ln2_g, ln2_b, hnh, hnl);

    // 6. FFN up + GELU
    dim3 gff1(FFD/BN, ROWS/BM);
    tc_gemm<2><<<gff1, 256, GEMM_SMEM>>>(hnh, hnl, win16, nullptr, nullptr,
                                         ffh, ffl, FFD, HID);

    // 7. FFN down + residual -> d_out
    dim3 gff2(HID/BN, ROWS/BM);
    tc_gemm<1><<<gff2, 256, GEMM_SMEM>>>(ffh, ffl, wout16, h, out,
                                         nullptr, nullptr, HID, FFD);
}

// round 10
// speedup vs baseline: 2.0492x; 1.3834x over previous
#include <cuda_runtime.h>
#include <cuda_fp16.h>
#include <math.h>
#include <cstdint>

#define BATCH 2
#define SEQ   2048
#define HID   2048
#define NHEAD 16
#define HDIM  128
#define FFD   8192
#define ROWS  (BATCH*SEQ)   // 4096
#define QKVLD (3*HID)       // 6144

// ---------------- scratch ---------------------------------------------------
__device__ float g_qkv[(size_t)ROWS*QKVLD];   // packed q|k|v (fp32)
__device__ float g_h [ROWS*HID];
__device__ __half g_xn16[ROWS*HID];
__device__ __half g_att16[ROWS*HID];
__device__ __half g_hn16[ROWS*HID];
__device__ __half g_ff16[(size_t)ROWS*FFD];
__device__ __half g_wqkv16[(size_t)HID*QKVLD];  // packed [K=HID][6144]
__device__ __half g_wo16[HID*HID];
__device__ __half g_win16[(size_t)HID*FFD];
__device__ __half g_wout16[(size_t)HID*FFD];

// ============================ helpers ========================================
__device__ __forceinline__ uint32_t smem_u32(const void* p) {
    uint32_t a;
    asm("{ .reg .u64 t; cvta.to.shared.u64 t, %1; cvt.u32.u64 %0, t; }"
        : "=r"(a) : "l"(p));
    return a;
}
__device__ __forceinline__ void cp16(uint32_t dst, const void* src) {
    asm volatile("cp.async.cg.shared.global [%0], [%1], 16;" :: "r"(dst), "l"(src));
}
__device__ __forceinline__ void cp_commit() { asm volatile("cp.async.commit_group;"); }
template<int N> __device__ __forceinline__ void cp_wait() {
    asm volatile("cp.async.wait_group %0;" :: "n"(N));
}
__device__ __forceinline__ void ldsm_x4(uint32_t* r, uint32_t addr) {
    asm volatile("ldmatrix.sync.aligned.m8n8.x4.shared.b16 {%0,%1,%2,%3}, [%4];"
        : "=r"(r[0]), "=r"(r[1]), "=r"(r[2]), "=r"(r[3]) : "r"(addr));
}
__device__ __forceinline__ void ldsm_x4_t(uint32_t* r, uint32_t addr) {
    asm volatile("ldmatrix.sync.aligned.m8n8.x4.trans.shared.b16 {%0,%1,%2,%3}, [%4];"
        : "=r"(r[0]), "=r"(r[1]), "=r"(r[2]), "=r"(r[3]) : "r"(addr));
}
__device__ __forceinline__ void mma_f16(float* c, const uint32_t* a, const uint32_t* b) {
    asm volatile("mma.sync.aligned.m16n8k16.row.col.f32.f16.f16.f32 "
        "{%0,%1,%2,%3}, {%4,%5,%6,%7}, {%8,%9}, {%0,%1,%2,%3};"
        : "+f"(c[0]), "+f"(c[1]), "+f"(c[2]), "+f"(c[3])
        : "r"(a[0]), "r"(a[1]), "r"(a[2]), "r"(a[3]), "r"(b[0]), "r"(b[1]));
}
__device__ __forceinline__ float gelu_tanh(float x) {
    float x3 = x * x * x;
    float t  = tanhf(0.7978845608028654f * (x + 0.044715f * x3));
    return 0.5f * x * (1.0f + t);
}

// ============================================================================
// fp16 tensor-core GEMM, fp32 accumulate: C = A16 * B16  (+epilogue)
// 2 CTAs/SM, 1 barrier per k-tile, early cp.async refill.
// ACT: 0 -> fp32 C, 1 -> fp32 C + Res, 2 -> GELU -> fp16 C
// ============================================================================
#define BM 128
#define BN 128
#define BKH 32
#define LDAH 40
#define LDBH 136
#define ASZH (BM*LDAH)      // 5120 halves
#define BSZH (BKH*LDBH)     // 4352 halves
#define STG 3
#define STAGEH (ASZH + BSZH)        // 9472 halves
#define GEMM_SMEM (STG*STAGEH*2)    // 56832 bytes -> 2 CTAs/SM

template<int ACT>
__global__ __launch_bounds__(256, 2) void tc_gemm(
    const __half* __restrict__ A16,
    const __half* __restrict__ B16,
    const float* __restrict__ Res, float* __restrict__ Cf,
    __half* __restrict__ C16,
    int N_, int K)
{
    extern __shared__ __align__(16) __half smem[];

    const int tid  = threadIdx.x;
    const int wid  = tid >> 5;
    const int lane = tid & 31;
    const int gid  = lane >> 2;
    const int tg   = lane & 3;
    const int wm   = wid & 3;
    const int wn   = wid >> 2;
    const int bm = blockIdx.y * BM;
    const int bn = blockIdx.x * BN;
    const int nK = K / BKH;

    const int a_m = lane & 15;
    const int a_k = (lane >> 4) * 8;
    const int b_k = ((lane >> 3) & 1) * 8 + (lane & 7);
    const int b_n = (lane >> 4) * 8;

    auto load_stage = [&](int s, int kt) {
        const int k0 = kt * BKH;
        __half* As = smem + s*STAGEH;
        __half* Bs = As + ASZH;
        #pragma unroll
        for (int i = 0; i < 2; i++) {
            const int c  = tid + 256*i;
            const int ar = c >> 2, ak = (c & 3) << 3;
            cp16(smem_u32(&As[ar*LDAH + ak]), &A16[(size_t)(bm + ar)*K + k0 + ak]);
            const int bk = c >> 4, bnn = (c & 15) << 3;
            cp16(smem_u32(&Bs[bk*LDBH + bnn]), &B16[(size_t)(k0 + bk)*N_ + bn + bnn]);
        }
        cp_commit();
    };

    float acc[2][8][4];
    #pragma unroll
    for (int mt = 0; mt < 2; mt++)
        #pragma unroll
        for (int nt = 0; nt < 8; nt++)
            #pragma unroll
            for (int r = 0; r < 4; r++) acc[mt][nt][r] = 0.0f;

    load_stage(0, 0);
    load_stage(1, 1);

    for (int kt = 0; kt < nK; kt++) {
        cp_wait<1>();
        __syncthreads();
        // refill stage whose readers finished at kt-1 (reg deps + barrier)
        if (kt + STG - 1 < nK)
            load_stage((kt + STG - 1) % STG, kt + STG - 1);

        const int s = kt % STG;
        const __half* As = smem + s*STAGEH;
        const __half* Bs = As + ASZH;

        #pragma unroll
        for (int kk = 0; kk < 2; kk++) {
            uint32_t af[2][4];
            #pragma unroll
            for (int mt = 0; mt < 2; mt++) {
                const int mrow = wm*32 + mt*16 + a_m;
                const int koff = kk*16 + a_k;
                ldsm_x4(af[mt], smem_u32(&As[mrow*LDAH + koff]));
            }
            uint32_t bf[4][4];
            #pragma unroll
            for (int ng = 0; ng < 4; ng++) {
                const int koff = kk*16 + b_k;
                const int noff = wn*64 + ng*16 + b_n;
                ldsm_x4_t(bf[ng], smem_u32(&Bs[koff*LDBH + noff]));
            }
            #pragma unroll
            for (int mt = 0; mt < 2; mt++)
                #pragma unroll
                for (int nt = 0; nt < 8; nt++)
                    mma_f16(acc[mt][nt], af[mt], &bf[nt >> 1][(nt & 1) * 2]);
        }
    }

    #pragma unroll
    for (int mt = 0; mt < 2; mt++) {
        #pragma unroll
        for (int half_ = 0; half_ < 2; half_++) {
            const int r = bm + wm*32 + mt*16 + gid + half_*8;
            #pragma unroll
            for (int nt = 0; nt < 8; nt++) {
                const int cc = bn + wn*64 + nt*8 + tg*2;
                float v0 = acc[mt][nt][half_*2 + 0];
                float v1 = acc[mt][nt][half_*2 + 1];
                if (ACT == 2) {
                    v0 = gelu_tanh(v0); v1 = gelu_tanh(v1);
                    *reinterpret_cast<__half2*>(&C16[(size_t)r*N_ + cc]) =
                        __halves2half2(__float2half_rn(v0), __float2half_rn(v1));
                } else {
                    if (ACT == 1) {
                        const float2 rr = *reinterpret_cast<const float2*>(&Res[(size_t)r*N_ + cc]);
                        v0 += rr.x; v1 += rr.y;
                    }
                    float2 o; o.x = v0; o.y = v1;
                    *reinterpret_cast<float2*>(&Cf[(size_t)r*N_ + cc]) = o;
                }
            }
        }
    }
}

// ------------- weight conversion: fp32 -> RN fp16 ---------------------------
__global__ void convqkv_kernel(const float* __restrict__ wq,
                               const float* __restrict__ wk,
                               const float* __restrict__ wv,
                               const float* __restrict__ wo,
                               __half* __restrict__ qkv16,
                               __half* __restrict__ wo16,
                               int n4)
{
    const int i = blockIdx.x*blockDim.x + threadIdx.x;
    if (i >= n4) return;
    const int y = blockIdx.y;
    const float* in = (y == 0) ? wq : (y == 1) ? wk : (y == 2) ? wv : wo;
    const int e   = i * 4;
    const int row = e >> 11;
    const int col = e & 2047;
    float4 v = reinterpret_cast<const float4*>(in)[i];
    __half2 p0 = __halves2half2(__float2half_rn(v.x), __float2half_rn(v.y));
    __half2 p1 = __halves2half2(__float2half_rn(v.z), __float2half_rn(v.w));
    __half* dst; size_t o;
    if (y < 3) { dst = qkv16; o = (size_t)row*QKVLD + y*HID + col; }
    else       { dst = wo16;  o = (size_t)row*HID + col; }
    reinterpret_cast<__half2*>(dst + o)[0] = p0;
    reinterpret_cast<__half2*>(dst + o)[1] = p1;
}
__global__ void conv2_kernel(const float* __restrict__ w0, __half* o0,
                             const float* __restrict__ w1, __half* o1,
                             int n4)
{
    const float* in = blockIdx.y ? w1 : w0;
    __half* dst = blockIdx.y ? o1 : o0;
    const int i = blockIdx.x*blockDim.x + threadIdx.x;
    if (i >= n4) return;
    float4 v = reinterpret_cast<const float4*>(in)[i];
    reinterpret_cast<__half2*>(dst)[2*i+0] =
        __halves2half2(__float2half_rn(v.x), __float2half_rn(v.y));
    reinterpret_cast<__half2*>(dst)[2*i+1] =
        __halves2half2(__float2half_rn(v.z), __float2half_rn(v.w));
}

// ---------------- LayerNorm -> fp16 output ----------------------------------
__global__ void ln_kernel(const float* __restrict__ x,
                          const float* __restrict__ g,
                          const float* __restrict__ b,
                          __half* __restrict__ o16)
{
    const int row = blockIdx.x;
    const int tid = threadIdx.x;
    const float* xr = x + (size_t)row * HID;

    float4 v0 = reinterpret_cast<const float4*>(xr)[tid];
    float4 v1 = reinterpret_cast<const float4*>(xr)[tid + 256];

    __shared__ float red[8];

    float s = v0.x+v0.y+v0.z+v0.w + v1.x+v1.y+v1.z+v1.w;
    #pragma unroll
    for (int o = 16; o > 0; o >>= 1) s += __shfl_xor_sync(0xffffffffu, s, o);
    if ((tid & 31) == 0) red[tid >> 5] = s;
    __syncthreads();
    float mu = (red[0]+red[1]+red[2]+red[3]+red[4]+red[5]+red[6]+red[7]) * (1.0f/HID);
    __syncthreads();

    float d0x=v0.x-mu, d0y=v0.y-mu, d0z=v0.z-mu, d0w=v0.w-mu;
    float d1x=v1.x-mu, d1y=v1.y-mu, d1z=v1.z-mu, d1w=v1.w-mu;
    float sq = d0x*d0x+d0y*d0y+d0z*d0z+d0w*d0w + d1x*d1x+d1y*d1y+d1z*d1z+d1w*d1w;
    #pragma unroll
    for (int o = 16; o > 0; o >>= 1) sq += __shfl_xor_sync(0xffffffffu, sq, o);
    if ((tid & 31) == 0) red[tid >> 5] = sq;
    __syncthreads();
    float var = (red[0]+red[1]+red[2]+red[3]+red[4]+red[5]+red[6]+red[7]) * (1.0f/HID);
    float rstd = rsqrtf(var + 1e-5f);

    float4 g0 = reinterpret_cast<const float4*>(g)[tid];
    float4 g1 = reinterpret_cast<const float4*>(g)[tid + 256];
    float4 b0 = reinterpret_cast<const float4*>(b)[tid];
    float4 b1 = reinterpret_cast<const float4*>(b)[tid + 256];

    const size_t base = (size_t)row * HID;
    reinterpret_cast<__half2*>(o16 + base)[tid*2+0] = __halves2half2(
        __float2half_rn(d0x*rstd*g0.x + b0.x), __float2half_rn(d0y*rstd*g0.y + b0.y));
    reinterpret_cast<__half2*>(o16 + base)[tid*2+1] = __halves2half2(
        __float2half_rn(d0z*rstd*g0.z + b0.z), __float2half_rn(d0w*rstd*g0.w + b0.w));
    reinterpret_cast<__half2*>(o16 + base)[(tid+256)*2+0] = __halves2half2(
        __float2half_rn(d1x*rstd*g1.x + b1.x), __float2half_rn(d1y*rstd*g1.y + b1.y));
    reinterpret_cast<__half2*>(o16 + base)[(tid+256)*2+1] = __halves2half2(
        __float2half_rn(d1z*rstd*g1.z + b1.z), __float2half_rn(d1w*rstd*g1.w + b1.w));
}

// ---------------- Flash attention (causal, fp32, packed QKV) ----------------
#define QSTRIDE 132
#define KSTRIDE 68
#define PSTRIDE 68

__global__ __launch_bounds__(256) void flash_kernel(
    const float* __restrict__ QKV,
    __half* __restrict__ O16)
{
    extern __shared__ float sm[];
    float* Qs = sm;
    float* Kt = Qs + 64*QSTRIDE;
    float* Vs = Kt + 128*KSTRIDE;
    float* Ps = Vs + 64*QSTRIDE;

    const int tid = threadIdx.x;
    const int tx = tid & 15;
    const int ty = tid >> 4;
    const int bh = blockIdx.y;
    const int b  = bh >> 4;
    const int h  = bh & 15;
    const int qb = blockIdx.x;
    const size_t rowbase = (size_t)b * SEQ;
    const int colbase = h * HDIM;
    const float scale = 0.088388347648318447f;

    #pragma unroll
    for (int it = 0; it < 8; ++it) {
        int idx = it * 256 + tid;
        int r  = idx >> 5;
        int c4 = (idx & 31) << 2;
        float4 qv = *reinterpret_cast<const float4*>(
            &QKV[(rowbase + qb*64 + r) * QKVLD + colbase + c4]);
        *reinterpret_cast<float4*>(&Qs[r*QSTRIDE + c4]) = qv;
    }

    float m[4], l[4], o[4][8];
    #pragma unroll
    for (int i = 0; i < 4; i++) {
        m[i] = -1e30f; l[i] = 0.0f;
        #pragma unroll
        for (int c = 0; c < 8; c++) o[i][c] = 0.0f;
    }

    for (int kb = 0; kb <= qb; ++kb) {
        __syncthreads();
        #pragma unroll
        for (int it = 0; it < 8; ++it) {
            int idx = it * 256 + tid;
            int r  = idx >> 5;
            int c4 = (idx & 31) << 2;
            const size_t grow = (rowbase + kb*64 + r) * (size_t)QKVLD + colbase + c4;
            float4 kv = *reinterpret_cast<const float4*>(&QKV[grow + HID]);
            Kt[(c4+0)*KSTRIDE + r] = kv.x;
            Kt[(c4+1)*KSTRIDE + r] = kv.y;
            Kt[(c4+2)*KSTRIDE + r] = kv.z;
            Kt[(c4+3)*KSTRIDE + r] = kv.w;
            float4 vv = *reinterpret_cast<const float4*>(&QKV[grow + 2*HID]);
            *reinterpret_cast<float4*>(&Vs[r*QSTRIDE + c4]) = vv;
        }
        __syncthreads();

        float s[4][4];
        #pragma unroll
        for (int i = 0; i < 4; i++)
            #pragma unroll
            for (int jj = 0; jj < 4; jj++) s[i][jj] = 0.0f;

        #pragma unroll 2
        for (int d4 = 0; d4 < HDIM/4; ++d4) {
            float4 kr[4];
            #pragma unroll
            for (int dd = 0; dd < 4; dd++)
                kr[dd] = *reinterpret_cast<const float4*>(&Kt[(d4*4 + dd)*KSTRIDE + tx*4]);
            #pragma unroll
            for (int i = 0; i < 4; i++) {
                const float4 q4 = *reinterpret_cast<const float4*>(&Qs[(ty*4 + i)*QSTRIDE + d4*4]);
                s[i][0] = fmaf(q4.x, kr[0].x, s[i][0]);
                s[i][1] = fmaf(q4.x, kr[0].y, s[i][1]);
                s[i][2] = fmaf(q4.x, kr[0].z, s[i][2]);
                s[i][3] = fmaf(q4.x, kr[0].w, s[i][3]);
                s[i][0] = fmaf(q4.y, kr[1].x, s[i][0]);
                s[i][1] = fmaf(q4.y, kr[1].y, s[i][1]);
                s[i][2] = fmaf(q4.y, kr[1].z, s[i][2]);
                s[i][3] = fmaf(q4.y, kr[1].w, s[i][3]);
                s[i][0] = fmaf(q4.z, kr[2].x, s[i][0]);
                s[i][1] = fmaf(q4.z, kr[2].y, s[i][1]);
                s[i][2] = fmaf(q4.z, kr[2].z, s[i][2]);
                s[i][3] = fmaf(q4.z, kr[2].w, s[i][3]);
                s[i][0] = fmaf(q4.w, kr[3].x, s[i][0]);
                s[i][1] = fmaf(q4.w, kr[3].y, s[i][1]);
                s[i][2] = fmaf(q4.w, kr[3].z, s[i][2]);
                s[i][3] = fmaf(q4.w, kr[3].w, s[i][3]);
            }
        }

        const bool diag = (kb == qb);
        #pragma unroll
        for (int i = 0; i < 4; i++) {
            const int qg = qb*64 + ty*4 + i;
            float mx = -1e30f;
            #pragma unroll
            for (int jj = 0; jj < 4; jj++) {
                float v = s[i][jj] * scale;
                if (diag && (kb*64 + tx*4 + jj) > qg) v = -1e30f;
                s[i][jj] = v;
                mx = fmaxf(mx, v);
            }
            #pragma unroll
            for (int off = 8; off > 0; off >>= 1)
                mx = fmaxf(mx, __shfl_xor_sync(0xffffffffu, mx, off));
            float mnew = fmaxf(m[i], mx);
            float corr = __expf(m[i] - mnew);
            float rs = 0.0f;
            #pragma unroll
            for (int jj = 0; jj < 4; jj++) {
                float p = __expf(s[i][jj] - mnew);
                s[i][jj] = p;
                rs += p;
            }
            #pragma unroll
            for (int off = 8; off > 0; off >>= 1)
                rs += __shfl_xor_sync(0xffffffffu, rs, off);
            l[i] = l[i]*corr + rs;
            m[i] = mnew;
            #pragma unroll
            for (int c = 0; c < 8; c++) o[i][c] *= corr;
            float4 pv; pv.x = s[i][0]; pv.y = s[i][1]; pv.z = s[i][2]; pv.w = s[i][3];
            *reinterpret_cast<float4*>(&Ps[(ty*4 + i)*PSTRIDE + tx*4]) = pv;
        }
        __syncthreads();

        #pragma unroll 2
        for (int j4 = 0; j4 < 16; ++j4) {
            float4 p4[4];
            #pragma unroll
            for (int i = 0; i < 4; i++)
                p4[i] = *reinterpret_cast<const float4*>(&Ps[(ty*4 + i)*PSTRIDE + j4*4]);
            #pragma unroll
            for (int jj = 0; jj < 4; jj++) {
                const int j = j4*4 + jj;
                const float4 va = *reinterpret_cast<const float4*>(&Vs[j*QSTRIDE + tx*4]);
                const float4 vb = *reinterpret_cast<const float4*>(&Vs[j*QSTRIDE + 64 + tx*4]);
                #pragma unroll
                for (int i = 0; i < 4; i++) {
                    const float p = (jj == 0) ? p4[i].x : (jj == 1) ? p4[i].y
                                  : (jj == 2) ? p4[i].z : p4[i].w;
                    o[i][0] = fmaf(p, va.x, o[i][0]);
                    o[i][1] = fmaf(p, va.y, o[i][1]);
                    o[i][2] = fmaf(p, va.z, o[i][2]);
                    o[i][3] = fmaf(p, va.w, o[i][3]);
                    o[i][4] = fmaf(p, vb.x, o[i][4]);
                    o[i][5] = fmaf(p, vb.y, o[i][5]);
                    o[i][6] = fmaf(p, vb.z, o[i][6]);
                    o[i][7] = fmaf(p, vb.w, o[i][7]);
                }
            }
        }
    }

    #pragma unroll
    for (int i = 0; i < 4; i++) {
        const float inv = 1.0f / l[i];
        const size_t r = rowbase + qb*64 + ty*4 + i;
        __half2* o0 = reinterpret_cast<__half2*>(&O16[r*HID + colbase + tx*4]);
        o0[0] = __halves2half2(__float2half_rn(o[i][0]*inv), __float2half_rn(o[i][1]*inv));
        o0[1] = __halves2half2(__float2half_rn(o[i][2]*inv), __float2half_rn(o[i][3]*inv));
        __half2* o1 = reinterpret_cast<__half2*>(&O16[r*HID + colbase + 64 + tx*4]);
        o1[0] = __halves2half2(__float2half_rn(o[i][4]*inv), __float2half_rn(o[i][5]*inv));
        o1[1] = __halves2half2(__float2half_rn(o[i][6]*inv), __float2half_rn(o[i][7]*inv));
    }
}

// ============================ host side =====================================
extern "C" void kernel_launch(void* const* d_in, const int* in_sizes, int n_in,
                              void* d_out, int out_size)
{
    const float* x     = (const float*)d_in[0];
    const float* wq    = (const float*)d_in[2];
    const float* wk    = (const float*)d_in[3];
    const float* wv    = (const float*)d_in[4];
    const float* wo    = (const float*)d_in[5];
    const float* w_in  = (const float*)d_in[6];
    const float* w_out = (const float*)d_in[7];
    const float* ln1_g = (const float*)d_in[8];
    const float* ln1_b = (const float*)d_in[9];
    const float* ln2_g = (const float*)d_in[10];
    const float* ln2_b = (const float*)d_in[11];
    float* out = (float*)d_out;

    float *qkv, *h;
    __half *xn16,*att16,*hn16,*ff16;
    __half *wqkv16,*wo16,*win16,*wout16;
    cudaGetSymbolAddress((void**)&qkv, g_qkv);
    cudaGetSymbolAddress((void**)&h,  g_h);
    cudaGetSymbolAddress((void**)&xn16, g_xn16);
    cudaGetSymbolAddress((void**)&att16, g_att16);
    cudaGetSymbolAddress((void**)&hn16, g_hn16);
    cudaGetSymbolAddress((void**)&ff16, g_ff16);
    cudaGetSymbolAddress((void**)&wqkv16, g_wqkv16);
    cudaGetSymbolAddress((void**)&wo16, g_wo16);
    cudaGetSymbolAddress((void**)&win16, g_win16);
    cudaGetSymbolAddress((void**)&wout16, g_wout16);

    cudaFuncSetAttribute(tc_gemm<0>, cudaFuncAttributeMaxDynamicSharedMemorySize, GEMM_SMEM);
    cudaFuncSetAttribute(tc_gemm<1>, cudaFuncAttributeMaxDynamicSharedMemorySize, GEMM_SMEM);
    cudaFuncSetAttribute(tc_gemm<2>, cudaFuncAttributeMaxDynamicSharedMemorySize, GEMM_SMEM);
    const int smem_flash = (64*QSTRIDE + 128*KSTRIDE + 64*QSTRIDE + 64*PSTRIDE) * 4;
    cudaFuncSetAttribute(flash_kernel, cudaFuncAttributeMaxDynamicSharedMemorySize, smem_flash);

    // 0. convert weights to RN-fp16
    {
        const int t = 256;
        dim3 gq((HID*HID/4 + t-1)/t, 4);
        convqkv_kernel<<<gq, t>>>(wq, wk, wv, wo, wqkv16, wo16, HID*HID/4);
        dim3 g2((HID*FFD/4 + t-1)/t, 2);
        conv2_kernel<<<g2, t>>>(w_in, win16, w_out, wout16, HID*FFD/4);
    }

    // 1. LN1 -> fp16
    ln_kernel<<<ROWS, 256>>>(x, ln1_g, ln1_b, xn16);

    // 2. fused QKV projection
    dim3 gqkv(QKVLD/BN, ROWS/BM);
    tc_gemm<0><<<gqkv, 256, GEMM_SMEM>>>(xn16, wqkv16, nullptr, qkv, nullptr,
                                         QKVLD, HID);

    // 3. causal flash attention
    dim3 gattn(SEQ/64, BATCH*NHEAD);
    flash_kernel<<<gattn, 256, smem_flash>>>(qkv, att16);

    // 4. output projection + residual -> h
    dim3 gproj(HID/BN, ROWS/BM);
    tc_gemm<1><<<gproj, 256, GEMM_SMEM>>>(att16, wo16, x, h, nullptr, HID, HID);

    // 5. LN2 -> fp16
    ln_kernel<<<ROWS, 256>>>(h, ln2_g, ln2_b, hn16);

    // 6. FFN up + GELU -> fp16
    dim3 gff1(FFD/BN, ROWS/BM);
    tc_gemm<2><<<gff1, 256, GEMM_SMEM>>>(hn16, win16, nullptr, nullptr, ff16,
                                         FFD, HID);

    // 7. FFN down + residual -> d_out
    dim3 gff2(HID/BN, ROWS/BM);
    tc_gemm<1><<<gff2, 256, GEMM_SMEM>>>(ff16, wout16, h, out, nullptr,
                                         HID, FFD);
}

// round 11
// speedup vs baseline: 3.3851x; 1.6519x over previous
#include <cuda_runtime.h>
#include <cuda_fp16.h>
#include <math.h>
#include <cstdint>

#define BATCH 2
#define SEQ   2048
#define HID   2048
#define NHEAD 16
#define HDIM  128
#define FFD   8192
#define ROWS  (BATCH*SEQ)   // 4096
#define QKVLD (3*HID)       // 6144

// ---------------- scratch ---------------------------------------------------
__device__ __half g_qkv16[(size_t)ROWS*QKVLD];  // packed q|k|v (fp16)
__device__ float g_h [ROWS*HID];
__device__ __half g_xn16[ROWS*HID];
__device__ __half g_att16[ROWS*HID];
__device__ __half g_hn16[ROWS*HID];
__device__ __half g_ff16[(size_t)ROWS*FFD];
__device__ __half g_wqkv16[(size_t)HID*QKVLD];
__device__ __half g_wo16[HID*HID];
__device__ __half g_win16[(size_t)HID*FFD];
__device__ __half g_wout16[(size_t)HID*FFD];

// ============================ helpers ========================================
__device__ __forceinline__ uint32_t smem_u32(const void* p) {
    uint32_t a;
    asm("{ .reg .u64 t; cvta.to.shared.u64 t, %1; cvt.u32.u64 %0, t; }"
        : "=r"(a) : "l"(p));
    return a;
}
__device__ __forceinline__ void cp16(uint32_t dst, const void* src) {
    asm volatile("cp.async.cg.shared.global [%0], [%1], 16;" :: "r"(dst), "l"(src));
}
__device__ __forceinline__ void cp_commit() { asm volatile("cp.async.commit_group;"); }
template<int N> __device__ __forceinline__ void cp_wait() {
    asm volatile("cp.async.wait_group %0;" :: "n"(N));
}
__device__ __forceinline__ void ldsm_x4(uint32_t* r, uint32_t addr) {
    asm volatile("ldmatrix.sync.aligned.m8n8.x4.shared.b16 {%0,%1,%2,%3}, [%4];"
        : "=r"(r[0]), "=r"(r[1]), "=r"(r[2]), "=r"(r[3]) : "r"(addr));
}
__device__ __forceinline__ void ldsm_x4_t(uint32_t* r, uint32_t addr) {
    asm volatile("ldmatrix.sync.aligned.m8n8.x4.trans.shared.b16 {%0,%1,%2,%3}, [%4];"
        : "=r"(r[0]), "=r"(r[1]), "=r"(r[2]), "=r"(r[3]) : "r"(addr));
}
__device__ __forceinline__ void mma_f16(float* c, const uint32_t* a, const uint32_t* b) {
    asm volatile("mma.sync.aligned.m16n8k16.row.col.f32.f16.f16.f32 "
        "{%0,%1,%2,%3}, {%4,%5,%6,%7}, {%8,%9}, {%0,%1,%2,%3};"
        : "+f"(c[0]), "+f"(c[1]), "+f"(c[2]), "+f"(c[3])
        : "r"(a[0]), "r"(a[1]), "r"(a[2]), "r"(a[3]), "r"(b[0]), "r"(b[1]));
}
__device__ __forceinline__ void mma_f16_b(float* c, const uint32_t* a,
                                          uint32_t b0, uint32_t b1) {
    asm volatile("mma.sync.aligned.m16n8k16.row.col.f32.f16.f16.f32 "
        "{%0,%1,%2,%3}, {%4,%5,%6,%7}, {%8,%9}, {%0,%1,%2,%3};"
        : "+f"(c[0]), "+f"(c[1]), "+f"(c[2]), "+f"(c[3])
        : "r"(a[0]), "r"(a[1]), "r"(a[2]), "r"(a[3]), "r"(b0), "r"(b1));
}
__device__ __forceinline__ float gelu_tanh(float x) {
    float x3 = x * x * x;
    float t  = tanhf(0.7978845608028654f * (x + 0.044715f * x3));
    return 0.5f * x * (1.0f + t);
}
__device__ __forceinline__ uint32_t pack_h2(float x, float y) {
    __half2 h = __halves2half2(__float2half_rn(x), __float2half_rn(y));
    return *reinterpret_cast<uint32_t*>(&h);
}

// ============================================================================
// fp16 tensor-core GEMM, fp32 accumulate.
// ACT: 0 -> fp16 C, 1 -> fp32 C + Res, 2 -> GELU -> fp16 C
// ============================================================================
#define BM 128
#define BN 128
#define BKH 32
#define LDAH 40
#define LDBH 136
#define ASZH (BM*LDAH)
#define BSZH (BKH*LDBH)
#define STG 3
#define STAGEH (ASZH + BSZH)
#define GEMM_SMEM (STG*STAGEH*2)

template<int ACT>
__global__ __launch_bounds__(256, 2) void tc_gemm(
    const __half* __restrict__ A16,
    const __half* __restrict__ B16,
    const float* __restrict__ Res, float* __restrict__ Cf,
    __half* __restrict__ C16,
    int N_, int K)
{
    extern __shared__ __align__(16) __half smem[];

    const int tid  = threadIdx.x;
    const int wid  = tid >> 5;
    const int lane = tid & 31;
    const int gid  = lane >> 2;
    const int tg   = lane & 3;
    const int wm   = wid & 3;
    const int wn   = wid >> 2;
    const int bm = blockIdx.y * BM;
    const int bn = blockIdx.x * BN;
    const int nK = K / BKH;

    const int a_m = lane & 15;
    const int a_k = (lane >> 4) * 8;
    const int b_k = ((lane >> 3) & 1) * 8 + (lane & 7);
    const int b_n = (lane >> 4) * 8;

    auto load_stage = [&](int s, int kt) {
        const int k0 = kt * BKH;
        __half* As = smem + s*STAGEH;
        __half* Bs = As + ASZH;
        #pragma unroll
        for (int i = 0; i < 2; i++) {
            const int c  = tid + 256*i;
            const int ar = c >> 2, ak = (c & 3) << 3;
            cp16(smem_u32(&As[ar*LDAH + ak]), &A16[(size_t)(bm + ar)*K + k0 + ak]);
            const int bk = c >> 4, bnn = (c & 15) << 3;
            cp16(smem_u32(&Bs[bk*LDBH + bnn]), &B16[(size_t)(k0 + bk)*N_ + bn + bnn]);
        }
        cp_commit();
    };

    float acc[2][8][4];
    #pragma unroll
    for (int mt = 0; mt < 2; mt++)
        #pragma unroll
        for (int nt = 0; nt < 8; nt++)
            #pragma unroll
            for (int r = 0; r < 4; r++) acc[mt][nt][r] = 0.0f;

    load_stage(0, 0);
    load_stage(1, 1);

    for (int kt = 0; kt < nK; kt++) {
        cp_wait<1>();
        __syncthreads();
        if (kt + STG - 1 < nK)
            load_stage((kt + STG - 1) % STG, kt + STG - 1);

        const int s = kt % STG;
        const __half* As = smem + s*STAGEH;
        const __half* Bs = As + ASZH;

        #pragma unroll
        for (int kk = 0; kk < 2; kk++) {
            uint32_t af[2][4];
            #pragma unroll
            for (int mt = 0; mt < 2; mt++) {
                const int mrow = wm*32 + mt*16 + a_m;
                const int koff = kk*16 + a_k;
                ldsm_x4(af[mt], smem_u32(&As[mrow*LDAH + koff]));
            }
            uint32_t bf[4][4];
            #pragma unroll
            for (int ng = 0; ng < 4; ng++) {
                const int koff = kk*16 + b_k;
                const int noff = wn*64 + ng*16 + b_n;
                ldsm_x4_t(bf[ng], smem_u32(&Bs[koff*LDBH + noff]));
            }
            #pragma unroll
            for (int mt = 0; mt < 2; mt++)
                #pragma unroll
                for (int nt = 0; nt < 8; nt++)
                    mma_f16(acc[mt][nt], af[mt], &bf[nt >> 1][(nt & 1) * 2]);
        }
    }

    #pragma unroll
    for (int mt = 0; mt < 2; mt++) {
        #pragma unroll
        for (int half_ = 0; half_ < 2; half_++) {
            const int r = bm + wm*32 + mt*16 + gid + half_*8;
            #pragma unroll
            for (int nt = 0; nt < 8; nt++) {
                const int cc = bn + wn*64 + nt*8 + tg*2;
                float v0 = acc[mt][nt][half_*2 + 0];
                float v1 = acc[mt][nt][half_*2 + 1];
                if (ACT == 0) {
                    *reinterpret_cast<__half2*>(&C16[(size_t)r*N_ + cc]) =
                        __halves2half2(__float2half_rn(v0), __float2half_rn(v1));
                } else if (ACT == 2) {
                    v0 = gelu_tanh(v0); v1 = gelu_tanh(v1);
                    *reinterpret_cast<__half2*>(&C16[(size_t)r*N_ + cc]) =
                        __halves2half2(__float2half_rn(v0), __float2half_rn(v1));
                } else {
                    const float2 rr = *reinterpret_cast<const float2*>(&Res[(size_t)r*N_ + cc]);
                    float2 o; o.x = v0 + rr.x; o.y = v1 + rr.y;
                    *reinterpret_cast<float2*>(&Cf[(size_t)r*N_ + cc]) = o;
                }
            }
        }
    }
}

// ------------- weight conversion: fp32 -> RN fp16 ---------------------------
__global__ void convqkv_kernel(const float* __restrict__ wq,
                               const float* __restrict__ wk,
                               const float* __restrict__ wv,
                               const float* __restrict__ wo,
                               __half* __restrict__ qkv16,
                               __half* __restrict__ wo16,
                               int n4)
{
    const int i = blockIdx.x*blockDim.x + threadIdx.x;
    if (i >= n4) return;
    const int y = blockIdx.y;
    const float* in = (y == 0) ? wq : (y == 1) ? wk : (y == 2) ? wv : wo;
    const int e   = i * 4;
    const int row = e >> 11;
    const int col = e & 2047;
    float4 v = reinterpret_cast<const float4*>(in)[i];
    __half2 p0 = __halves2half2(__float2half_rn(v.x), __float2half_rn(v.y));
    __half2 p1 = __halves2half2(__float2half_rn(v.z), __float2half_rn(v.w));
    __half* dst; size_t o;
    if (y < 3) { dst = qkv16; o = (size_t)row*QKVLD + y*HID + col; }
    else       { dst = wo16;  o = (size_t)row*HID + col; }
    reinterpret_cast<__half2*>(dst + o)[0] = p0;
    reinterpret_cast<__half2*>(dst + o)[1] = p1;
}
__global__ void conv2_kernel(const float* __restrict__ w0, __half* o0,
                             const float* __restrict__ w1, __half* o1,
                             int n4)
{
    const float* in = blockIdx.y ? w1 : w0;
    __half* dst = blockIdx.y ? o1 : o0;
    const int i = blockIdx.x*blockDim.x + threadIdx.x;
    if (i >= n4) return;
    float4 v = reinterpret_cast<const float4*>(in)[i];
    reinterpret_cast<__half2*>(dst)[2*i+0] =
        __halves2half2(__float2half_rn(v.x), __float2half_rn(v.y));
    reinterpret_cast<__half2*>(dst)[2*i+1] =
        __halves2half2(__float2half_rn(v.z), __float2half_rn(v.w));
}

// ---------------- LayerNorm -> fp16 output ----------------------------------
__global__ void ln_kernel(const float* __restrict__ x,
                          const float* __restrict__ g,
                          const float* __restrict__ b,
                          __half* __restrict__ o16)
{
    const int row = blockIdx.x;
    const int tid = threadIdx.x;
    const float* xr = x + (size_t)row * HID;

    float4 v0 = reinterpret_cast<const float4*>(xr)[tid];
    float4 v1 = reinterpret_cast<const float4*>(xr)[tid + 256];

    __shared__ float red[8];

    float s = v0.x+v0.y+v0.z+v0.w + v1.x+v1.y+v1.z+v1.w;
    #pragma unroll
    for (int o = 16; o > 0; o >>= 1) s += __shfl_xor_sync(0xffffffffu, s, o);
    if ((tid & 31) == 0) red[tid >> 5] = s;
    __syncthreads();
    float mu = (red[0]+red[1]+red[2]+red[3]+red[4]+red[5]+red[6]+red[7]) * (1.0f/HID);
    __syncthreads();

    float d0x=v0.x-mu, d0y=v0.y-mu, d0z=v0.z-mu, d0w=v0.w-mu;
    float d1x=v1.x-mu, d1y=v1.y-mu, d1z=v1.z-mu, d1w=v1.w-mu;
    float sq = d0x*d0x+d0y*d0y+d0z*d0z+d0w*d0w + d1x*d1x+d1y*d1y+d1z*d1z+d1w*d1w;
    #pragma unroll
    for (int o = 16; o > 0; o >>= 1) sq += __shfl_xor_sync(0xffffffffu, sq, o);
    if ((tid & 31) == 0) red[tid >> 5] = sq;
    __syncthreads();
    float var = (red[0]+red[1]+red[2]+red[3]+red[4]+red[5]+red[6]+red[7]) * (1.0f/HID);
    float rstd = rsqrtf(var + 1e-5f);

    float4 g0 = reinterpret_cast<const float4*>(g)[tid];
    float4 g1 = reinterpret_cast<const float4*>(g)[tid + 256];
    float4 b0 = reinterpret_cast<const float4*>(b)[tid];
    float4 b1 = reinterpret_cast<const float4*>(b)[tid + 256];

    const size_t base = (size_t)row * HID;
    reinterpret_cast<__half2*>(o16 + base)[tid*2+0] = __halves2half2(
        __float2half_rn(d0x*rstd*g0.x + b0.x), __float2half_rn(d0y*rstd*g0.y + b0.y));
    reinterpret_cast<__half2*>(o16 + base)[tid*2+1] = __halves2half2(
        __float2half_rn(d0z*rstd*g0.z + b0.z), __float2half_rn(d0w*rstd*g0.w + b0.w));
    reinterpret_cast<__half2*>(o16 + base)[(tid+256)*2+0] = __halves2half2(
        __float2half_rn(d1x*rstd*g1.x + b1.x), __float2half_rn(d1y*rstd*g1.y + b1.y));
    reinterpret_cast<__half2*>(o16 + base)[(tid+256)*2+1] = __halves2half2(
        __float2half_rn(d1z*rstd*g1.z + b1.z), __float2half_rn(d1w*rstd*g1.w + b1.w));
}

// ---------------- Flash attention: fp16 mma.sync tensor cores ---------------
// 128 threads (4 warps). Warp w owns Q rows 16w..16w+15 of a 64-row q-block.
// S = Q K^T via m16n8k16 (K [n][k] row-major -> non-trans ldsm, pairs r0/r2).
// P repacked in-register to A-fragments; PV via trans ldsm on V ([k][n]).
#define FSTR 136
#define FLASH_SMEM (3*64*FSTR*2)   // Q,K,V tiles: 52224 bytes

__global__ __launch_bounds__(128, 3) void flash_kernel(
    const __half* __restrict__ QKV,
    __half* __restrict__ O16)
{
    extern __shared__ __align__(16) __half fsm[];
    __half* Qs = fsm;
    __half* Ks = Qs + 64*FSTR;
    __half* Vs = Ks + 64*FSTR;

    const int tid = threadIdx.x;
    const int w   = tid >> 5;
    const int lane = tid & 31;
    const int gid = lane >> 2;
    const int tg  = lane & 3;
    const int bh = blockIdx.y;
    const int b  = bh >> 4;
    const int h  = bh & 15;
    const int qb = blockIdx.x;
    const size_t rowbase = (size_t)b * SEQ;
    const int colbase = h * HDIM;
    const float scale = 0.088388347648318447f;

    const int a_r = lane & 15;
    const int a_c = (lane >> 4) * 8;
    const int t_k = ((lane >> 3) & 1) * 8 + (lane & 7);
    const int t_n = (lane >> 4) * 8;

    // load Q tile (64 x 128 fp16)
    #pragma unroll
    for (int it = 0; it < 8; ++it) {
        int idx = it*128 + tid;
        int r = idx >> 4;
        int c8 = (idx & 15) << 3;
        cp16(smem_u32(&Qs[r*FSTR + c8]),
             &QKV[(rowbase + qb*64 + r)*(size_t)QKVLD + colbase + c8]);
    }
    cp_commit();

    float m0 = -1e30f, m1 = -1e30f, l0 = 0.0f, l1 = 0.0f;
    float oacc[16][4];
    #pragma unroll
    for (int t = 0; t < 16; t++)
        #pragma unroll
        for (int r = 0; r < 4; r++) oacc[t][r] = 0.0f;

    const int qr0 = qb*64 + w*16 + gid;   // global q row (lo)
    const int qr1 = qr0 + 8;

    for (int kb = 0; kb <= qb; ++kb) {
        __syncthreads();
        #pragma unroll
        for (int it = 0; it < 8; ++it) {
            int idx = it*128 + tid;
            int r = idx >> 4;
            int c8 = (idx & 15) << 3;
            const size_t grow = (rowbase + kb*64 + r)*(size_t)QKVLD + colbase + c8;
            cp16(smem_u32(&Ks[r*FSTR + c8]), &QKV[grow + HID]);
            cp16(smem_u32(&Vs[r*FSTR + c8]), &QKV[grow + 2*HID]);
        }
        cp_commit();
        cp_wait<0>();
        __syncthreads();

        // ---- S = Q K^T (warp: m16, n64, k128) ----
        float sacc[8][4];
        #pragma unroll
        for (int j = 0; j < 8; j++)
            #pragma unroll
            for (int r = 0; r < 4; r++) sacc[j][r] = 0.0f;

        #pragma unroll
        for (int kc = 0; kc < 8; kc++) {
            uint32_t af[4];
            ldsm_x4(af, smem_u32(&Qs[(w*16 + a_r)*FSTR + kc*16 + a_c]));
            #pragma unroll
            for (int ng = 0; ng < 4; ng++) {
                uint32_t bf[4];
                ldsm_x4(bf, smem_u32(&Ks[(ng*16 + a_r)*FSTR + kc*16 + a_c]));
                mma_f16_b(sacc[2*ng+0], af, bf[0], bf[2]);
                mma_f16_b(sacc[2*ng+1], af, bf[1], bf[3]);
            }
        }

        // ---- online softmax ----
        const bool diag = (kb == qb);
        float mx0 = -1e30f, mx1 = -1e30f;
        #pragma unroll
        for (int j = 0; j < 8; j++) {
            #pragma unroll
            for (int cc = 0; cc < 2; cc++) {
                const int colg = kb*64 + j*8 + 2*tg + cc;
                float v0 = sacc[j][cc]   * scale;
                float v1 = sacc[j][2+cc] * scale;
                if (diag) {
                    if (colg > qr0) v0 = -1e30f;
                    if (colg > qr1) v1 = -1e30f;
                }
                sacc[j][cc] = v0; sacc[j][2+cc] = v1;
                mx0 = fmaxf(mx0, v0); mx1 = fmaxf(mx1, v1);
            }
        }
        mx0 = fmaxf(mx0, __shfl_xor_sync(0xffffffffu, mx0, 1));
        mx0 = fmaxf(mx0, __shfl_xor_sync(0xffffffffu, mx0, 2));
        mx1 = fmaxf(mx1, __shfl_xor_sync(0xffffffffu, mx1, 1));
        mx1 = fmaxf(mx1, __shfl_xor_sync(0xffffffffu, mx1, 2));

        const float mn0 = fmaxf(m0, mx0), mn1 = fmaxf(m1, mx1);
        const float c0 = __expf(m0 - mn0), c1 = __expf(m1 - mn1);
        float rs0 = 0.0f, rs1 = 0.0f;
        uint32_t ph0[8], ph1[8];
        #pragma unroll
        for (int j = 0; j < 8; j++) {
            const float p00 = __expf(sacc[j][0] - mn0);
            const float p01 = __expf(sacc[j][1] - mn0);
            const float p10 = __expf(sacc[j][2] - mn1);
            const float p11 = __expf(sacc[j][3] - mn1);
            rs0 += p00 + p01; rs1 += p10 + p11;
            ph0[j] = pack_h2(p00, p01);
            ph1[j] = pack_h2(p10, p11);
        }
        rs0 += __shfl_xor_sync(0xffffffffu, rs0, 1);
        rs0 += __shfl_xor_sync(0xffffffffu, rs0, 2);
        rs1 += __shfl_xor_sync(0xffffffffu, rs1, 1);
        rs1 += __shfl_xor_sync(0xffffffffu, rs1, 2);
        l0 = l0*c0 + rs0;  m0 = mn0;
        l1 = l1*c1 + rs1;  m1 = mn1;

        #pragma unroll
        for (int t = 0; t < 16; t++) {
            oacc[t][0] *= c0; oacc[t][1] *= c0;
            oacc[t][2] *= c1; oacc[t][3] *= c1;
        }

        // ---- O += P V  (k = 64 kv rows, n = 128) ----
        #pragma unroll
        for (int kt = 0; kt < 4; kt++) {
            uint32_t pa[4] = { ph0[2*kt], ph1[2*kt], ph0[2*kt+1], ph1[2*kt+1] };
            #pragma unroll
            for (int ng = 0; ng < 8; ng++) {
                uint32_t bf[4];
                ldsm_x4_t(bf, smem_u32(&Vs[(kt*16 + t_k)*FSTR + ng*16 + t_n]));
                mma_f16_b(oacc[2*ng+0], pa, bf[0], bf[1]);
                mma_f16_b(oacc[2*ng+1], pa, bf[2], bf[3]);
            }
        }
    }

    // ---- epilogue ----
    const float inv0 = 1.0f / l0, inv1 = 1.0f / l1;
    const size_t r0 = rowbase + qr0;
    const size_t r1 = rowbase + qr1;
    #pragma unroll
    for (int t = 0; t < 16; t++) {
        const int col = colbase + t*8 + 2*tg;
        *reinterpret_cast<__half2*>(&O16[r0*HID + col]) =
            __halves2half2(__float2half_rn(oacc[t][0]*inv0),
                           __float2half_rn(oacc[t][1]*inv0));
        *reinterpret_cast<__half2*>(&O16[r1*HID + col]) =
            __halves2half2(__float2half_rn(oacc[t][2]*inv1),
                           __float2half_rn(oacc[t][3]*inv1));
    }
}

// ============================ host side =====================================
extern "C" void kernel_launch(void* const* d_in, const int* in_sizes, int n_in,
                              void* d_out, int out_size)
{
    const float* x     = (const float*)d_in[0];
    const float* wq    = (const float*)d_in[2];
    const float* wk    = (const float*)d_in[3];
    const float* wv    = (const float*)d_in[4];
    const float* wo    = (const float*)d_in[5];
    const float* w_in  = (const float*)d_in[6];
    const float* w_out = (const float*)d_in[7];
    const float* ln1_g = (const float*)d_in[8];
    const float* ln1_b = (const float*)d_in[9];
    const float* ln2_g = (const float*)d_in[10];
    const float* ln2_b = (const float*)d_in[11];
    float* out = (float*)d_out;

    float *h;
    __half *qkv16,*xn16,*att16,*hn16,*ff16;
    __half *wqkv16,*wo16,*win16,*wout16;
    cudaGetSymbolAddress((void**)&qkv16, g_qkv16);
    cudaGetSymbolAddress((void**)&h,  g_h);
    cudaGetSymbolAddress((void**)&xn16, g_xn16);
    cudaGetSymbolAddress((void**)&att16, g_att16);
    cudaGetSymbolAddress((void**)&hn16, g_hn16);
    cudaGetSymbolAddress((void**)&ff16, g_ff16);
    cudaGetSymbolAddress((void**)&wqkv16, g_wqkv16);
    cudaGetSymbolAddress((void**)&wo16, g_wo16);
    cudaGetSymbolAddress((void**)&win16, g_win16);
    cudaGetSymbolAddress((void**)&wout16, g_wout16);

    cudaFuncSetAttribute(tc_gemm<0>, cudaFuncAttributeMaxDynamicSharedMemorySize, GEMM_SMEM);
    cudaFuncSetAttribute(tc_gemm<1>, cudaFuncAttributeMaxDynamicSharedMemorySize, GEMM_SMEM);
    cudaFuncSetAttribute(tc_gemm<2>, cudaFuncAttributeMaxDynamicSharedMemorySize, GEMM_SMEM);
    cudaFuncSetAttribute(flash_kernel, cudaFuncAttributeMaxDynamicSharedMemorySize, FLASH_SMEM);

    // 0. convert weights to RN-fp16
    {
        const int t = 256;
        dim3 gq((HID*HID/4 + t-1)/t, 4);
        convqkv_kernel<<<gq, t>>>(wq, wk, wv, wo, wqkv16, wo16, HID*HID/4);
        dim3 g2((HID*FFD/4 + t-1)/t, 2);
        conv2_kernel<<<g2, t>>>(w_in, win16, w_out, wout16, HID*FFD/4);
    }

    // 1. LN1 -> fp16
    ln_kernel<<<ROWS, 256>>>(x, ln1_g, ln1_b, xn16);

    // 2. fused QKV projection -> fp16
    dim3 gqkv(QKVLD/BN, ROWS/BM);
    tc_gemm<0><<<gqkv, 256, GEMM_SMEM>>>(xn16, wqkv16, nullptr, nullptr, qkv16,
                                         QKVLD, HID);

    // 3. causal flash attention (tensor cores) -> fp16
    dim3 gattn(SEQ/64, BATCH*NHEAD);
    flash_kernel<<<gattn, 128, FLASH_SMEM>>>(qkv16, att16);

    // 4. output projection + residual -> h (fp32)
    dim3 gproj(HID/BN, ROWS/BM);
    tc_gemm<1><<<gproj, 256, GEMM_SMEM>>>(att16, wo16, x, h, nullptr, HID, HID);

    // 5. LN2 -> fp16
    ln_kernel<<<ROWS, 256>>>(h, ln2_g, ln2_b, hn16);

    // 6. FFN up + GELU -> fp16
    dim3 gff1(FFD/BN, ROWS/BM);
    tc_gemm<2><<<gff1, 256, GEMM_SMEM>>>(hn16, win16, nullptr, nullptr, ff16,
                                         FFD, HID);

    // 7. FFN down + residual -> d_out
    dim3 gff2(HID/BN, ROWS/BM);
    tc_gemm<1><<<gff2, 256, GEMM_SMEM>>>(ff16, wout16, h, out, nullptr,
                                         HID, FFD);
}